// round 8
// baseline (speedup 1.0000x reference)
#include <cuda_runtime.h>
#include <math.h>

#define NRENDER 16        // NF(2) * T(8)
#define NFACE_C 1024
#define HW 128
#define TEXW 256
#define KSZ 11

// ---------------- device scratch ----------------
__device__ float g_RT[NRENDER][12];             // 9 rotation + 3 translation
__device__ float g_plane[NRENDER][NFACE_C][16]; // A0,B0,C0,A1,B1,C1,A2,B2,C2,zA,zB,zC,xmin,xmax,ymin,ymax
__device__ float g_uvp[NRENDER][NFACE_C][8];    // uA,uB,uC,vA,vB,vC,pad,pad
__device__ float g_img[NRENDER][4][HW][HW];     // rgb + raw mask

__device__ __forceinline__ unsigned fkey(float f) {
    unsigned u = __float_as_uint(f);
    return u ^ ((u & 0x80000000u) ? 0xFFFFFFFFu : 0x80000000u);
}

// ---------------- quaternion helper ----------------
__device__ __forceinline__ void quat_to_R_dev(const float* q, float scale, float* R) {
    float c = q[0], x = q[1], y = q[2], z = q[3];
    float sin2 = x*x + y*y + z*z;
    float sint = sqrtf(fmaxf(sin2, 1e-12f));
    float tt = 2.0f * ((c < 0.0f) ? atan2f(-sint, -c) : atan2f(sint, c));
    float k = (sin2 > 1e-12f) ? (tt / sint) : 2.0f;
    float ax = k*x*scale, ay = k*y*scale, az = k*z*scale;
    float th = sqrtf(ax*ax + ay*ay + az*az);
    float inv = 1.0f / fmaxf(th, 1e-8f);
    float ux = ax*inv, uy = ay*inv, uz = az*inv;
    float s = sinf(th), co = cosf(th), oc = 1.0f - co;
    R[0] = 1.0f + oc*(-(uy*uy + uz*uz));
    R[1] = -s*uz + oc*(ux*uy);
    R[2] =  s*uy + oc*(ux*uz);
    R[3] =  s*uz + oc*(ux*uy);
    R[4] = 1.0f + oc*(-(ux*ux + uz*uz));
    R[5] = -s*ux + oc*(uy*uz);
    R[6] = -s*uy + oc*(ux*uz);
    R[7] =  s*ux + oc*(uy*uz);
    R[8] = 1.0f + oc*(-(ux*ux + uy*uy));
}

// ---------------- rotation chains: one thread per render ----------------
__global__ void rot_kernel(const float* __restrict__ quat, const float* __restrict__ trans) {
    int r = threadIdx.x;
    if (r >= NRENDER) return;
    int f = r >> 3, t = r & 7;
    float R0[9], Rs[9];
    quat_to_R_dev(&quat[f*8 + 4], 1.0f, R0);     // q[:,f,1]
    quat_to_R_dev(&quat[f*8 + 0], 0.125f, Rs);   // q[:,f,0]/T/ROT_DIV
    float Rm[9];
    #pragma unroll
    for (int k = 0; k < 9; k++) Rm[k] = R0[k];
    for (int s = 0; s < t; s++) {
        float Nw[9];
        #pragma unroll
        for (int i = 0; i < 3; i++)
            #pragma unroll
            for (int k = 0; k < 3; k++)
                Nw[i*3+k] = Rm[i*3+0]*Rs[0*3+k] + Rm[i*3+1]*Rs[1*3+k] + Rm[i*3+2]*Rs[2*3+k];
        #pragma unroll
        for (int k = 0; k < 9; k++) Rm[k] = Nw[k];
    }
    #pragma unroll
    for (int k = 0; k < 9; k++) g_RT[r][k] = Rm[k];
    float ti = (float)t / 7.0f;
    #pragma unroll
    for (int a = 0; a < 3; a++)
        g_RT[r][9+a] = trans[a*4 + f*2 + 1] + ti * trans[a*4 + f*2 + 0];
}

// ---------------- per (render, face) plane setup ----------------
// grid (4, NRENDER), block 256
__global__ void face_kernel(const float* __restrict__ verts, const int* __restrict__ faces,
                            const float* __restrict__ ff) {
    int r = blockIdx.y;
    int fc = blockIdx.x * 256 + threadIdx.x;
    float R[12];
    #pragma unroll
    for (int k = 0; k < 12; k++) R[k] = __ldg(&g_RT[r][k]);
    const float invt = 1.0f / tanf(0.3925f);   // 1/tan(FOV/2); px==py since W==H
    float sx[3], sy[3], zz[3], P[3][3];
    #pragma unroll
    for (int k = 0; k < 3; k++) {
        int vi = faces[fc*3 + k];
        float vx = verts[vi*3+0], vy = verts[vi*3+1], vz = verts[vi*3+2];
        float Xc = R[0]*vx + R[1]*vy + R[2]*vz + R[9];
        float Yc = R[3]*vx + R[4]*vy + R[5]*vz + R[10];
        float Zc = R[6]*vx + R[7]*vy + R[8]*vz + R[11] - 2.0f;   // CAM_D
        P[k][0] = Xc; P[k][1] = Yc; P[k][2] = Zc;
        float invnz = 1.0f / (-Zc);
        sx[k] = (Xc * invt) * invnz;
        sy[k] = (Yc * invt) * invnz;
        zz[k] = Zc;
    }
    float e1x = P[1][0]-P[0][0], e1y = P[1][1]-P[0][1], e1z = P[1][2]-P[0][2];
    float e2x = P[2][0]-P[0][0], e2y = P[2][1]-P[0][1], e2z = P[2][2]-P[0][2];
    float nx = e1y*e2z - e1z*e2y;
    float ny = e1z*e2x - e1x*e2z;
    float nzv = e1x*e2y - e1y*e2x;
    float nz = nzv / (sqrtf(nx*nx + ny*ny + nzv*nzv) + 1e-8f);

    float area = (sx[1]-sx[0])*(sy[2]-sy[0]) - (sy[1]-sy[0])*(sx[2]-sx[0]);
    if (fabsf(area) < 1e-10f) area = 1e-10f;
    float ia = 1.0f / area;
    float A0 = -(sy[2]-sy[1])*ia, B0 = (sx[2]-sx[1])*ia;
    float C0 = ((sy[2]-sy[1])*sx[1] - (sx[2]-sx[1])*sy[1])*ia;
    float A1 = -(sy[0]-sy[2])*ia, B1 = (sx[0]-sx[2])*ia;
    float C1 = ((sy[0]-sy[2])*sx[2] - (sx[0]-sx[2])*sy[2])*ia;
    float A2 = -(sy[1]-sy[0])*ia, B2 = (sx[1]-sx[0])*ia;
    float C2 = ((sy[1]-sy[0])*sx[0] - (sx[1]-sx[0])*sy[0])*ia;
    float zA = A0*zz[0] + A1*zz[1] + A2*zz[2];
    float zB = B0*zz[0] + B1*zz[1] + B2*zz[2];
    float zC = C0*zz[0] + C1*zz[1] + C2*zz[2];

    float xmin, xmax, ymin, ymax;
    if (nz > 0.0f) {
        xmin = fminf(sx[0], fminf(sx[1], sx[2]));
        xmax = fmaxf(sx[0], fmaxf(sx[1], sx[2]));
        ymin = fminf(sy[0], fminf(sy[1], sy[2]));
        ymax = fmaxf(sy[0], fmaxf(sy[1], sy[2]));
    } else {
        xmin = 1e30f; xmax = -1e30f; ymin = 1e30f; ymax = -1e30f;  // never passes cull
    }
    float* pl = g_plane[r][fc];
    pl[0]=A0; pl[1]=B0; pl[2]=C0; pl[3]=A1; pl[4]=B1; pl[5]=C1;
    pl[6]=A2; pl[7]=B2; pl[8]=C2; pl[9]=zA; pl[10]=zB; pl[11]=zC;
    pl[12]=xmin; pl[13]=xmax; pl[14]=ymin; pl[15]=ymax;

    float u0 = ff[fc*6+0], v0 = ff[fc*6+1];
    float u1 = ff[fc*6+2], v1 = ff[fc*6+3];
    float u2 = ff[fc*6+4], v2 = ff[fc*6+5];
    float* up = g_uvp[r][fc];
    up[0] = A0*u0 + A1*u1 + A2*u2;
    up[1] = B0*u0 + B1*u1 + B2*u2;
    up[2] = C0*u0 + C1*u1 + C2*u2;
    up[3] = A0*v0 + A1*v1 + A2*v2;
    up[4] = B0*v0 + B1*v1 + B2*v2;
    up[5] = C0*v0 + C1*v1 + C2*v2;
}

// ---------------- rasterize + texture sample ----------------
// grid: (32 tiles, 16 renders), block 256. Tile = 16 wide x 32 tall,
// 2 px/thread (rows i0, i0+16, same column). 48KB dynamic -> 4 blocks/SM.
__global__ void __launch_bounds__(256) raster_kernel(const float* __restrict__ tex) {
    extern __shared__ float sm[];         // 12288 floats = 48KB
    __shared__ unsigned s_key[NFACE_C];   // zmax keys: partial at [p], full at [1023-p]
    __shared__ int s_fid[NFACE_C];        // face ids, same layout
    __shared__ int s_np, s_nf;
    __shared__ unsigned s_M;
    int r = blockIdx.y;
    int tile = blockIdx.x;
    int tx = tile & 7, ty = tile >> 3;    // 8 x-tiles (16 wide), 4 y-tiles (32 tall)
    int lj = threadIdx.x & 15, li = threadIdx.x >> 4;   // li 0..15
    int j = tx*16 + lj, i0 = ty*32 + li;
    const float step = 2.0f / 127.0f;
    const float dY = -16.0f * step;
    float X  = -1.0f + (float)j * step;
    float Y0 =  1.0f - (float)i0 * step;
    float tX0 = -1.0f + (float)(tx*16) * step;
    float tX1 = -1.0f + (float)(tx*16 + 15) * step;
    float tY0 =  1.0f - (float)(ty*32) * step;          // top (max Y)
    float tY1 =  1.0f - (float)(ty*32 + 31) * step;     // bottom (min Y)

    if (threadIdx.x == 0) { s_np = 0; s_nf = 0; s_M = 0u; }
    __syncthreads();

    for (int fc = threadIdx.x; fc < NFACE_C; fc += 256) {
        const float* pl = g_plane[r][fc];
        float4 bb = *(const float4*)(pl + 12);
        if (!(bb.x <= tX1 && bb.y >= tX0 && bb.z <= tY0 && bb.w >= tY1)) continue;
        float4 a = *(const float4*)(pl + 0);
        float4 b = *(const float4*)(pl + 4);
        float4 c = *(const float4*)(pl + 8);
        bool reject = false, full = true;
        {
            float A[3] = {a.x, a.w, b.z}, Bc[3] = {a.y, b.x, b.w}, Cc[3] = {a.z, b.y, c.x};
            #pragma unroll
            for (int e = 0; e < 3; e++) {
                float e00 = fmaf(A[e], tX0, fmaf(Bc[e], tY0, Cc[e]));
                float e01 = fmaf(A[e], tX1, fmaf(Bc[e], tY0, Cc[e]));
                float e10 = fmaf(A[e], tX0, fmaf(Bc[e], tY1, Cc[e]));
                float e11 = fmaf(A[e], tX1, fmaf(Bc[e], tY1, Cc[e]));
                float mn = fminf(fminf(e00, e01), fminf(e10, e11));
                float mx = fmaxf(fmaxf(e00, e01), fmaxf(e10, e11));
                if (mx < 0.0f) reject = true;
                if (mn < 0.0f) full = false;
            }
        }
        if (reject) continue;
        float z00 = fmaf(c.y, tX0, fmaf(c.z, tY0, c.w));
        float z01 = fmaf(c.y, tX1, fmaf(c.z, tY0, c.w));
        float z10 = fmaf(c.y, tX0, fmaf(c.z, tY1, c.w));
        float z11 = fmaf(c.y, tX1, fmaf(c.z, tY1, c.w));
        float zmx = fmaxf(fmaxf(z00, z01), fmaxf(z10, z11));
        if (full) {
            float zmn = fminf(fminf(z00, z01), fminf(z10, z11));
            atomicMax(&s_M, fkey(zmn - 1e-6f));
            int p = atomicAdd(&s_nf, 1);
            float* d = sm + 12288 - 4*(p+1);
            d[0] = c.y; d[1] = c.z; d[2] = c.w;
            s_fid[1023 - p] = fc;
            s_key[1023 - p] = fkey(zmx);
        } else {
            int p = atomicAdd(&s_np, 1);
            float* d = sm + p*12;
            *(float4*)(d + 0) = a;
            *(float4*)(d + 4) = b;
            *(float4*)(d + 8) = c;
            s_fid[p] = fc;
            s_key[p] = fkey(zmx);
        }
    }
    __syncthreads();
    int np = s_np, nf = s_nf;
    unsigned M = s_M;

    float bz0 = -3.0e38f, bz1 = -3.0e38f;
    int   bf0 = 0x7fffffff, bf1 = 0x7fffffff;
    int   hit0 = (nf > 0) ? 1 : 0, hit1 = hit0;

    for (int q = 0; q < nf; q++) {
        if (s_key[1023 - q] < M) continue;
        const float* d = sm + 12288 - 4*(q+1);
        float zx = d[0], zy = d[1], zw = d[2];
        int fid = s_fid[1023 - q];
        float z = fmaf(zx, X, fmaf(zy, Y0, zw));
        if (z > bz0 || (z == bz0 && fid < bf0)) { bz0 = z; bf0 = fid; }
        z += zy * dY;
        if (z > bz1 || (z == bz1 && fid < bf1)) { bz1 = z; bf1 = fid; }
    }
    for (int q = 0; q < np; q++) {
        if (s_key[q] < M) continue;
        const float* d = sm + q*12;
        float4 a = *(const float4*)(d + 0);
        float4 b = *(const float4*)(d + 4);
        float4 c = *(const float4*)(d + 8);
        int fid = s_fid[q];
        float b0 = fmaf(a.x, X, fmaf(a.y, Y0, a.z));
        float b1 = fmaf(a.w, X, fmaf(b.x, Y0, b.y));
        float b2 = fmaf(b.z, X, fmaf(b.w, Y0, c.x));
        float z  = fmaf(c.y, X, fmaf(c.z, Y0, c.w));
        if (fminf(b0, fminf(b1, b2)) >= 0.0f) {
            hit0 = 1;
            if (z > bz0 || (z == bz0 && fid < bf0)) { bz0 = z; bf0 = fid; }
        }
        b0 += a.y*dY; b1 += b.x*dY; b2 += b.w*dY; z += c.z*dY;
        if (fminf(b0, fminf(b1, b2)) >= 0.0f) {
            hit1 = 1;
            if (z > bz1 || (z == bz1 && fid < bf1)) { bz1 = z; bf1 = fid; }
        }
    }

    #pragma unroll
    for (int k = 0; k < 2; k++) {
        int i = i0 + 16*k;
        int hit_i = k ? hit1 : hit0;
        int best_f = k ? bf1 : bf0;
        float Yk = 1.0f - (float)i * step;
        float u = 0.0f, v = 0.0f;
        if (hit_i) {
            const float* up = g_uvp[r][best_f];
            u = fmaf(up[0], X, fmaf(up[1], Yk, up[2]));
            v = fmaf(up[3], X, fmaf(up[4], Yk, up[5]));
        }
        float xf = u * 255.0f;
        float yf = (1.0f - v) * 255.0f;
        float x0 = fminf(fmaxf(floorf(xf), 0.0f), 254.0f);
        float y0 = fminf(fmaxf(floorf(yf), 0.0f), 254.0f);
        float fx = xf - x0, fy = yf - y0;
        int xi = (int)x0, yi = (int)y0;
        int base = yi * TEXW + xi;
        #pragma unroll
        for (int cch = 0; cch < 3; cch++) {
            const float* tc = tex + cch * (TEXW*TEXW);
            float t00 = __ldg(tc + base);
            float t01 = __ldg(tc + base + 1);
            float t10 = __ldg(tc + base + TEXW);
            float t11 = __ldg(tc + base + TEXW + 1);
            float val = t00*(1.0f-fx)*(1.0f-fy) + t01*fx*(1.0f-fy)
                      + t10*(1.0f-fx)*fy        + t11*fx*fy;
            g_img[r][cch][i][j] = val;
        }
        g_img[r][3][i][j] = (float)hit_i;
    }
}

// ---------------- tiled fused epilogue ----------------
// grid (16 tiles, NRENDER, 4), block 256 as 32x8.
// z=0 -> MASK channel (long pole, launched FIRST); z=1..3 -> RGB.
// Vertical blurs use an 11-deep rolling register window, order bit-exact.
#define GW0 1.4867195147e-06f
#define GW1 1.3383022576e-04f
#define GW2 4.4318484119e-03f
#define GW3 5.3990966513e-02f
#define GW4 2.4197072452e-01f
#define GW5 3.9894228040e-01f

__global__ void __launch_bounds__(256) post_kernel(float* __restrict__ out) {
    extern __shared__ float sm[];
    const float GW[KSZ] = {GW0,GW1,GW2,GW3,GW4,GW5,GW4,GW3,GW2,GW1,GW0};
    int tile = blockIdx.x, r = blockIdx.y;
    int c = (blockIdx.z + 3) & 3;           // z=0 -> c=3 (mask first)
    int tx = tile & 3, ty = tile >> 2;      // 4x4 tiles of 32x32
    int lx = threadIdx.x & 31, ly = threadIdx.x >> 5;   // 32x8

    if (c < 3) {
        // ---- RGB: 43x42 padded halo-5 load, vblur(window) -> 32x42, hblur -> 32x32 ----
        float* bufIn  = sm;                  // 43*42 (row 42 = scratch pad for window overrun)
        float* bufMid = sm + 43*42;          // 32 rows x 42 cols
        const int gy0 = ty*32 - 5, gx0 = tx*32 - 5;
        for (int li = ly; li < 42; li += 8) {
            int gi = gy0 + li;
            bool rowok = (gi >= 0 && gi < HW);
            {   int lj = lx;       int gj = gx0 + lj;
                bufIn[li*42 + lj] = (rowok && gj >= 0 && gj < HW) ? g_img[r][c][gi][gj] : 0.0f; }
            if (lx < 10) { int lj = lx + 32; int gj = gx0 + lj;
                bufIn[li*42 + lj] = (rowok && gj >= 0 && gj < HW) ? g_img[r][c][gi][gj] : 0.0f; }
        }
        __syncthreads();
        // vblur: thread ly owns rows [ly*4, ly*4+4), rolling window of 11
        {
            int r0 = ly * 4;
            #pragma unroll
            for (int cb = 0; cb < 2; cb++) {
                int lj = lx + cb*32;
                if (cb == 0 || lx < 10) {
                    float w[KSZ];
                    #pragma unroll
                    for (int k = 0; k < KSZ; k++) w[k] = bufIn[(r0 + k)*42 + lj];
                    #pragma unroll
                    for (int o = 0; o < 4; o++) {
                        float acc = 0.0f;
                        #pragma unroll
                        for (int k = 0; k < KSZ; k++) acc = fmaf(GW[k], w[k], acc);
                        bufMid[(r0 + o)*42 + lj] = acc;
                        #pragma unroll
                        for (int k = 0; k < KSZ-1; k++) w[k] = w[k+1];
                        w[KSZ-1] = bufIn[(r0 + o + KSZ)*42 + lj];   // row <= 42 (pad row)
                    }
                }
            }
        }
        __syncthreads();
        for (int li = ly; li < 32; li += 8) {
            float acc = 0.0f;
            #pragma unroll
            for (int k = 0; k < KSZ; k++) acc = fmaf(GW[k], bufMid[li*42 + lx + k], acc);
            out[((r*4 + c) << 14) + (ty*32 + li)*HW + tx*32 + lx] = acc;
        }
        return;
    }

    // ---- MASK: 74x74 halo-21, erode + 4 blur passes with shrinking margins ----
    float* bufA = sm;            // 74*74 = 5476
    float* bufB = sm + 5476;
    const int gy0 = ty*32 - 21, gx0 = tx*32 - 21;
    // load raw mask, +INF outside image (erode input)
    for (int li = ly; li < 74; li += 8) {
        int gi = gy0 + li;
        bool rowok = (gi >= 0 && gi < HW);
        #pragma unroll
        for (int cb = 0; cb < 3; cb++) {
            int lj = lx + cb*32;
            if (lj < 74) {
                int gj = gx0 + lj;
                bufA[li*74 + lj] = (rowok && gj >= 0 && gj < HW) ? g_img[r][3][gi][gj] : 3.0e38f;
            }
        }
    }
    __syncthreads();
    // erode margin-1 [1,73): unconditional 3x3 min (INF pad); gate output to 0 outside image
    for (int li = 1 + ly; li < 73; li += 8) {
        int gi = gy0 + li;
        #pragma unroll
        for (int cb = 0; cb < 3; cb++) {
            int lj = 1 + lx + cb*32;
            if (lj < 73) {
                int gj = gx0 + lj;
                const float* rm = bufA + (li-1)*74 + lj;
                const float* r0 = bufA + li*74 + lj;
                const float* rp = bufA + (li+1)*74 + lj;
                float m = fminf(fminf(fminf(rm[-1], rm[0]), fminf(rm[1], r0[-1])),
                                fminf(fminf(r0[0], r0[1]), fminf(fminf(rp[-1], rp[0]), rp[1])));
                bool inimg = (gi >= 0 && gi < HW && gj >= 0 && gj < HW);
                bufB[li*74 + lj] = inimg ? m : 0.0f;
            }
        }
    }
    __syncthreads();
    // vblur margin-6 rows [6,68): window, thread ly owns rows [6+ly*8, min(+8,68))
    {
        int r0 = 6 + ly * 8;
        int rend = min(r0 + 8, 68);
        #pragma unroll
        for (int cb = 0; cb < 2; cb++) {
            int lj = 6 + lx + cb*32;
            if (lj < 68) {
                float w[KSZ];
                #pragma unroll
                for (int k = 0; k < KSZ; k++) w[k] = bufB[(r0 + k - 5)*74 + lj];
                for (int li = r0; li < rend; li++) {
                    float acc = 0.0f;
                    #pragma unroll
                    for (int k = 0; k < KSZ; k++) acc = fmaf(GW[k], w[k], acc);
                    int gi = gy0 + li, gj = gx0 + lj;
                    bool inimg = (gi >= 0 && gi < HW && gj >= 0 && gj < HW);
                    bufA[li*74 + lj] = inimg ? acc : 0.0f;
                    #pragma unroll
                    for (int k = 0; k < KSZ-1; k++) w[k] = w[k+1];
                    w[KSZ-1] = bufB[(li + 6)*74 + lj];   // row <= 73, in-bounds
                }
            }
        }
    }
    __syncthreads();
    // hblur margin-11 [11,63)
    for (int li = 11 + ly; li < 63; li += 8) {
        int gi = gy0 + li;
        #pragma unroll
        for (int cb = 0; cb < 2; cb++) {
            int lj = 11 + lx + cb*32;
            if (lj < 63) {
                float acc = 0.0f;
                #pragma unroll
                for (int k = 0; k < KSZ; k++) acc = fmaf(GW[k], bufA[li*74 + lj + k - 5], acc);
                int gj = gx0 + lj;
                bool inimg = (gi >= 0 && gi < HW && gj >= 0 && gj < HW);
                bufB[li*74 + lj] = inimg ? acc : 0.0f;
            }
        }
    }
    __syncthreads();
    // vblur margin-16 rows [16,58): window, thread ly owns rows [16+ly*6, min(+6,58))
    {
        int r0 = 16 + ly * 6;
        int rend = min(r0 + 6, 58);
        #pragma unroll
        for (int cb = 0; cb < 2; cb++) {
            int lj = 16 + lx + cb*32;
            if (lj < 58) {
                float w[KSZ];
                #pragma unroll
                for (int k = 0; k < KSZ; k++) w[k] = bufB[(r0 + k - 5)*74 + lj];
                for (int li = r0; li < rend; li++) {
                    float acc = 0.0f;
                    #pragma unroll
                    for (int k = 0; k < KSZ; k++) acc = fmaf(GW[k], w[k], acc);
                    int gi = gy0 + li, gj = gx0 + lj;
                    bool inimg = (gi >= 0 && gi < HW && gj >= 0 && gj < HW);
                    bufA[li*74 + lj] = inimg ? acc : 0.0f;
                    #pragma unroll
                    for (int k = 0; k < KSZ-1; k++) w[k] = w[k+1];
                    w[KSZ-1] = bufB[(li + 6)*74 + lj];   // row <= 63, in-bounds
                }
            }
        }
    }
    __syncthreads();
    // hblur margin-21 [21,53) -> final 32x32 (always in-image)
    for (int li = 21 + ly; li < 53; li += 8) {
        int lj = 21 + lx;
        float acc = 0.0f;
        #pragma unroll
        for (int k = 0; k < KSZ; k++) acc = fmaf(GW[k], bufA[li*74 + lj + k - 5], acc);
        out[((r*4 + 3) << 14) + (gy0 + li)*HW + gx0 + lj] = acc;
    }
}

// ---------------- launcher ----------------
extern "C" void kernel_launch(void* const* d_in, const int* in_sizes, int n_in,
                              void* d_out, int out_size) {
    const float* vertices  = (const float*)d_in[0];
    const float* quat      = (const float*)d_in[1];
    const float* trans     = (const float*)d_in[2];
    const float* face_ff   = (const float*)d_in[4];
    const float* tex       = (const float*)d_in[5];
    const int*   faces     = (const int*)d_in[6];
    float* out = (float*)d_out;

    static bool attr_set = false;
    if (!attr_set) {
        cudaFuncSetAttribute(raster_kernel, cudaFuncAttributeMaxDynamicSharedMemorySize, 49152);
        cudaFuncSetAttribute(post_kernel,   cudaFuncAttributeMaxDynamicSharedMemorySize, 45056);
        attr_set = true;
    }

    rot_kernel<<<1, 16>>>(quat, trans);
    face_kernel<<<dim3(4, NRENDER), 256>>>(vertices, faces, face_ff);
    raster_kernel<<<dim3(32, NRENDER), 256, 49152>>>(tex);
    post_kernel<<<dim3(16, NRENDER, 4), 256, 45056>>>(out);
}

// round 9
// speedup vs baseline: 1.1959x; 1.1959x over previous
#include <cuda_runtime.h>
#include <math.h>

#define NRENDER 16        // NF(2) * T(8)
#define NFACE_C 1024
#define HW 128
#define TEXW 256
#define KSZ 11

// ---------------- device scratch ----------------
__device__ float g_RT[NRENDER][12];             // 9 rotation + 3 translation
__device__ float g_plane[NRENDER][NFACE_C][16]; // A0,B0,C0,A1,B1,C1,A2,B2,C2,zA,zB,zC,xmin,xmax,ymin,ymax
__device__ float g_uvp[NRENDER][NFACE_C][8];    // uA,uB,uC,vA,vB,vC,pad,pad
__device__ float g_img[NRENDER][4][HW][HW];     // rgb + raw mask
__device__ float g_w21[11][21];                 // border-corrected composed blur weights

// 11-tap gaussian literals (sigma=1), center at index 5
#define GW0 1.4867195147e-06f
#define GW1 1.3383022576e-04f
#define GW2 4.4318484119e-03f
#define GW3 5.3990966513e-02f
#define GW4 2.4197072452e-01f
#define GW5 3.9894228040e-01f

__device__ __forceinline__ unsigned fkey(float f) {
    unsigned u = __float_as_uint(f);
    return u ^ ((u & 0x80000000u) ? 0xFFFFFFFFu : 0x80000000u);
}

// ---------------- quaternion helper ----------------
__device__ __forceinline__ void quat_to_R_dev(const float* q, float scale, float* R) {
    float c = q[0], x = q[1], y = q[2], z = q[3];
    float sin2 = x*x + y*y + z*z;
    float sint = sqrtf(fmaxf(sin2, 1e-12f));
    float tt = 2.0f * ((c < 0.0f) ? atan2f(-sint, -c) : atan2f(sint, c));
    float k = (sin2 > 1e-12f) ? (tt / sint) : 2.0f;
    float ax = k*x*scale, ay = k*y*scale, az = k*z*scale;
    float th = sqrtf(ax*ax + ay*ay + az*az);
    float inv = 1.0f / fmaxf(th, 1e-8f);
    float ux = ax*inv, uy = ay*inv, uz = az*inv;
    float s = sinf(th), co = cosf(th), oc = 1.0f - co;
    R[0] = 1.0f + oc*(-(uy*uy + uz*uz));
    R[1] = -s*uz + oc*(ux*uy);
    R[2] =  s*uy + oc*(ux*uz);
    R[3] =  s*uz + oc*(ux*uy);
    R[4] = 1.0f + oc*(-(ux*ux + uz*uz));
    R[5] = -s*ux + oc*(uy*uz);
    R[6] = -s*uy + oc*(ux*uz);
    R[7] =  s*ux + oc*(uy*uz);
    R[8] = 1.0f + oc*(-(ux*ux + uy*uy));
}

// ---------------- rotation chains + border weight table ----------------
__global__ void rot_kernel(const float* __restrict__ quat, const float* __restrict__ trans) {
    int r = threadIdx.x;
    if (r < NRENDER) {
        int f = r >> 3, t = r & 7;
        float R0[9], Rs[9];
        quat_to_R_dev(&quat[f*8 + 4], 1.0f, R0);     // q[:,f,1]
        quat_to_R_dev(&quat[f*8 + 0], 0.125f, Rs);   // q[:,f,0]/T/ROT_DIV
        float Rm[9];
        #pragma unroll
        for (int k = 0; k < 9; k++) Rm[k] = R0[k];
        for (int s = 0; s < t; s++) {
            float Nw[9];
            #pragma unroll
            for (int i = 0; i < 3; i++)
                #pragma unroll
                for (int k = 0; k < 3; k++)
                    Nw[i*3+k] = Rm[i*3+0]*Rs[0*3+k] + Rm[i*3+1]*Rs[1*3+k] + Rm[i*3+2]*Rs[2*3+k];
            #pragma unroll
            for (int k = 0; k < 9; k++) Rm[k] = Nw[k];
        }
        #pragma unroll
        for (int k = 0; k < 9; k++) g_RT[r][k] = Rm[k];
        float ti = (float)t / 7.0f;
        #pragma unroll
        for (int a = 0; a < 3; a++)
            g_RT[r][9+a] = trans[a*4 + f*2 + 1] + ti * trans[a*4 + f*2 + 0];
    }
    // composed-blur weight rows for image-border outputs: row b (distance from
    // top edge, 0..10; 10 == interior). tab[b][t] = weight of input row j=b+t-10
    // for output row b of V-blur applied twice with per-pass zero padding:
    //   W = sum_{k in [0,127] ∩ [b-5,b+5] ∩ [j-5,j+5]} g[k-b+5]*g[j-k+5]
    int b = threadIdx.x - NRENDER;
    if (b >= 0 && b < 11) {
        const float g[KSZ] = {GW0,GW1,GW2,GW3,GW4,GW5,GW4,GW3,GW2,GW1,GW0};
        for (int t = 0; t < 21; t++) {
            int j = b + t - 10;
            float w = 0.0f;
            if (j >= 0) {
                int kmin = max(0, max(b-5, j-5));
                int kmax = min(b+5, j+5);
                for (int k = kmin; k <= kmax; k++)
                    w += g[k-b+5] * g[j-k+5];
            }
            g_w21[b][t] = w;
        }
    }
}

// ---------------- per (render, face) plane setup ----------------
// grid (4, NRENDER), block 256
__global__ void face_kernel(const float* __restrict__ verts, const int* __restrict__ faces,
                            const float* __restrict__ ff) {
    int r = blockIdx.y;
    int fc = blockIdx.x * 256 + threadIdx.x;
    float R[12];
    #pragma unroll
    for (int k = 0; k < 12; k++) R[k] = __ldg(&g_RT[r][k]);
    const float invt = 1.0f / tanf(0.3925f);   // 1/tan(FOV/2); px==py since W==H
    float sx[3], sy[3], zz[3], P[3][3];
    #pragma unroll
    for (int k = 0; k < 3; k++) {
        int vi = faces[fc*3 + k];
        float vx = verts[vi*3+0], vy = verts[vi*3+1], vz = verts[vi*3+2];
        float Xc = R[0]*vx + R[1]*vy + R[2]*vz + R[9];
        float Yc = R[3]*vx + R[4]*vy + R[5]*vz + R[10];
        float Zc = R[6]*vx + R[7]*vy + R[8]*vz + R[11] - 2.0f;   // CAM_D
        P[k][0] = Xc; P[k][1] = Yc; P[k][2] = Zc;
        float invnz = 1.0f / (-Zc);
        sx[k] = (Xc * invt) * invnz;
        sy[k] = (Yc * invt) * invnz;
        zz[k] = Zc;
    }
    float e1x = P[1][0]-P[0][0], e1y = P[1][1]-P[0][1], e1z = P[1][2]-P[0][2];
    float e2x = P[2][0]-P[0][0], e2y = P[2][1]-P[0][1], e2z = P[2][2]-P[0][2];
    float nx = e1y*e2z - e1z*e2y;
    float ny = e1z*e2x - e1x*e2z;
    float nzv = e1x*e2y - e1y*e2x;
    float nz = nzv / (sqrtf(nx*nx + ny*ny + nzv*nzv) + 1e-8f);

    float area = (sx[1]-sx[0])*(sy[2]-sy[0]) - (sy[1]-sy[0])*(sx[2]-sx[0]);
    if (fabsf(area) < 1e-10f) area = 1e-10f;
    float ia = 1.0f / area;
    float A0 = -(sy[2]-sy[1])*ia, B0 = (sx[2]-sx[1])*ia;
    float C0 = ((sy[2]-sy[1])*sx[1] - (sx[2]-sx[1])*sy[1])*ia;
    float A1 = -(sy[0]-sy[2])*ia, B1 = (sx[0]-sx[2])*ia;
    float C1 = ((sy[0]-sy[2])*sx[2] - (sx[0]-sx[2])*sy[2])*ia;
    float A2 = -(sy[1]-sy[0])*ia, B2 = (sx[1]-sx[0])*ia;
    float C2 = ((sy[1]-sy[0])*sx[0] - (sx[1]-sx[0])*sy[0])*ia;
    float zA = A0*zz[0] + A1*zz[1] + A2*zz[2];
    float zB = B0*zz[0] + B1*zz[1] + B2*zz[2];
    float zC = C0*zz[0] + C1*zz[1] + C2*zz[2];

    float xmin, xmax, ymin, ymax;
    if (nz > 0.0f) {
        xmin = fminf(sx[0], fminf(sx[1], sx[2]));
        xmax = fmaxf(sx[0], fmaxf(sx[1], sx[2]));
        ymin = fminf(sy[0], fminf(sy[1], sy[2]));
        ymax = fmaxf(sy[0], fmaxf(sy[1], sy[2]));
    } else {
        xmin = 1e30f; xmax = -1e30f; ymin = 1e30f; ymax = -1e30f;  // never passes cull
    }
    float* pl = g_plane[r][fc];
    pl[0]=A0; pl[1]=B0; pl[2]=C0; pl[3]=A1; pl[4]=B1; pl[5]=C1;
    pl[6]=A2; pl[7]=B2; pl[8]=C2; pl[9]=zA; pl[10]=zB; pl[11]=zC;
    pl[12]=xmin; pl[13]=xmax; pl[14]=ymin; pl[15]=ymax;

    float u0 = ff[fc*6+0], v0 = ff[fc*6+1];
    float u1 = ff[fc*6+2], v1 = ff[fc*6+3];
    float u2 = ff[fc*6+4], v2 = ff[fc*6+5];
    float* up = g_uvp[r][fc];
    up[0] = A0*u0 + A1*u1 + A2*u2;
    up[1] = B0*u0 + B1*u1 + B2*u2;
    up[2] = C0*u0 + C1*u1 + C2*u2;
    up[3] = A0*v0 + A1*v1 + A2*v2;
    up[4] = B0*v0 + B1*v1 + B2*v2;
    up[5] = C0*v0 + C1*v1 + C2*v2;
}

// ---------------- rasterize + texture sample (round-7 known-good) ----------------
// grid: (64 tiles, 16 renders), block 256 = 16x16 px (1 px/thread).
// 12-float partial records (48KB dynamic) + static fid/key arrays -> 4 blocks/SM.
__global__ void __launch_bounds__(256) raster_kernel(const float* __restrict__ tex) {
    extern __shared__ float sm[];         // 12288 floats = 48KB
    __shared__ unsigned s_key[NFACE_C];   // zmax keys: partial at [p], full at [1023-p]
    __shared__ int s_fid[NFACE_C];        // face ids, same layout
    __shared__ int s_np, s_nf;
    __shared__ unsigned s_M;
    int r = blockIdx.y;
    int tile = blockIdx.x;
    int tx = tile & 7, ty = tile >> 3;
    int lj = threadIdx.x & 15, li = threadIdx.x >> 4;
    int j = tx*16 + lj, i = ty*16 + li;
    const float step = 2.0f / 127.0f;
    float X = -1.0f + (float)j * step;
    float Y =  1.0f - (float)i * step;
    float tX0 = -1.0f + (float)(tx*16) * step;
    float tX1 = -1.0f + (float)(tx*16 + 15) * step;
    float tY0 =  1.0f - (float)(ty*16) * step;
    float tY1 =  1.0f - (float)(ty*16 + 15) * step;

    if (threadIdx.x == 0) { s_np = 0; s_nf = 0; s_M = 0u; }
    __syncthreads();

    for (int fc = threadIdx.x; fc < NFACE_C; fc += 256) {
        const float* pl = g_plane[r][fc];
        float4 bb = *(const float4*)(pl + 12);
        if (!(bb.x <= tX1 && bb.y >= tX0 && bb.z <= tY0 && bb.w >= tY1)) continue;
        float4 a = *(const float4*)(pl + 0);
        float4 b = *(const float4*)(pl + 4);
        float4 c = *(const float4*)(pl + 8);
        bool reject = false, full = true;
        {
            float A[3] = {a.x, a.w, b.z}, Bc[3] = {a.y, b.x, b.w}, Cc[3] = {a.z, b.y, c.x};
            #pragma unroll
            for (int e = 0; e < 3; e++) {
                float e00 = fmaf(A[e], tX0, fmaf(Bc[e], tY0, Cc[e]));
                float e01 = fmaf(A[e], tX1, fmaf(Bc[e], tY0, Cc[e]));
                float e10 = fmaf(A[e], tX0, fmaf(Bc[e], tY1, Cc[e]));
                float e11 = fmaf(A[e], tX1, fmaf(Bc[e], tY1, Cc[e]));
                float mn = fminf(fminf(e00, e01), fminf(e10, e11));
                float mx = fmaxf(fmaxf(e00, e01), fmaxf(e10, e11));
                if (mx < 0.0f) reject = true;
                if (mn < 0.0f) full = false;
            }
        }
        if (reject) continue;
        float z00 = fmaf(c.y, tX0, fmaf(c.z, tY0, c.w));
        float z01 = fmaf(c.y, tX1, fmaf(c.z, tY0, c.w));
        float z10 = fmaf(c.y, tX0, fmaf(c.z, tY1, c.w));
        float z11 = fmaf(c.y, tX1, fmaf(c.z, tY1, c.w));
        float zmx = fmaxf(fmaxf(z00, z01), fmaxf(z10, z11));
        if (full) {
            float zmn = fminf(fminf(z00, z01), fminf(z10, z11));
            atomicMax(&s_M, fkey(zmn - 1e-6f));
            int p = atomicAdd(&s_nf, 1);
            float* d = sm + 12288 - 4*(p+1);
            d[0] = c.y; d[1] = c.z; d[2] = c.w;
            s_fid[1023 - p] = fc;
            s_key[1023 - p] = fkey(zmx);
        } else {
            int p = atomicAdd(&s_np, 1);
            float* d = sm + p*12;
            *(float4*)(d + 0) = a;
            *(float4*)(d + 4) = b;
            *(float4*)(d + 8) = c;
            s_fid[p] = fc;
            s_key[p] = fkey(zmx);
        }
    }
    __syncthreads();
    int np = s_np, nf = s_nf;
    unsigned M = s_M;

    float best_z = -3.0e38f;
    int   best_f = 0x7fffffff;
    int   hit_i  = (nf > 0) ? 1 : 0;

    for (int q = 0; q < nf; q++) {
        if (s_key[1023 - q] < M) continue;
        const float4 zr = *(const float4*)(sm + 12288 - 4*(q+1));
        float z = fmaf(zr.x, X, fmaf(zr.y, Y, zr.z));
        int fid = s_fid[1023 - q];
        if (z > best_z || (z == best_z && fid < best_f)) { best_z = z; best_f = fid; }
    }
    for (int q = 0; q < np; q++) {
        if (s_key[q] < M) continue;
        const float* d = sm + q*12;
        float4 a = *(const float4*)(d + 0);
        float4 b = *(const float4*)(d + 4);
        float4 c = *(const float4*)(d + 8);
        int fid = s_fid[q];
        float b0 = fmaf(a.x, X, fmaf(a.y, Y, a.z));
        float b1 = fmaf(a.w, X, fmaf(b.x, Y, b.y));
        float b2 = fmaf(b.z, X, fmaf(b.w, Y, c.x));
        float z  = fmaf(c.y, X, fmaf(c.z, Y, c.w));
        bool inside = (fminf(b0, fminf(b1, b2)) >= 0.0f);
        if (inside) {
            hit_i = 1;
            if (z > best_z || (z == best_z && fid < best_f)) { best_z = z; best_f = fid; }
        }
    }

    float u = 0.0f, v = 0.0f;
    if (hit_i) {
        const float* up = g_uvp[r][best_f];
        u = fmaf(up[0], X, fmaf(up[1], Y, up[2]));
        v = fmaf(up[3], X, fmaf(up[4], Y, up[5]));
    }
    float xf = u * 255.0f;
    float yf = (1.0f - v) * 255.0f;
    float x0 = fminf(fmaxf(floorf(xf), 0.0f), 254.0f);
    float y0 = fminf(fmaxf(floorf(yf), 0.0f), 254.0f);
    float fx = xf - x0, fy = yf - y0;
    int xi = (int)x0, yi = (int)y0;
    int base = yi * TEXW + xi;
    #pragma unroll
    for (int cch = 0; cch < 3; cch++) {
        const float* tc = tex + cch * (TEXW*TEXW);
        float t00 = __ldg(tc + base);
        float t01 = __ldg(tc + base + 1);
        float t10 = __ldg(tc + base + TEXW);
        float t11 = __ldg(tc + base + TEXW + 1);
        float val = t00*(1.0f-fx)*(1.0f-fy) + t01*fx*(1.0f-fy)
                  + t10*(1.0f-fx)*fy        + t11*fx*fy;
        g_img[r][cch][i][j] = val;
    }
    g_img[r][3][i][j] = (float)hit_i;
}

// ---------------- tiled fused epilogue ----------------
// grid (16 tiles, NRENDER, 4), block 256 as 32x8.
// z=0 -> MASK (long pole, launched FIRST); z=1..3 -> RGB.
// Mask double-blur collapsed to ONE 21-tap pass per axis (V^2 then H^2);
// image-border outputs use exact clip-corrected weights from g_w21.
__global__ void __launch_bounds__(256) post_kernel(float* __restrict__ out) {
    extern __shared__ float sm[];
    const float GW[KSZ] = {GW0,GW1,GW2,GW3,GW4,GW5,GW4,GW3,GW2,GW1,GW0};
    // 21-tap autoconvolution of GW (interior rows), symmetric
    const float W21[21] = {
        2.2103349e-12f, 3.9795740e-10f, 3.1088500e-08f, 1.3467706e-06f,
        3.4812100e-05f, 5.4450606e-04f, 5.1673262e-03f, 2.9729460e-02f,
        1.0378766e-01f, 2.1967292e-01f, 2.8212397e-01f, 2.1967292e-01f,
        1.0378766e-01f, 2.9729460e-02f, 5.1673262e-03f, 5.4450606e-04f,
        3.4812100e-05f, 1.3467706e-06f, 3.1088500e-08f, 3.9795740e-10f,
        2.2103349e-12f };
    int tile = blockIdx.x, r = blockIdx.y;
    int c = (blockIdx.z + 3) & 3;           // z=0 -> c=3 (mask first)
    int tx = tile & 3, ty = tile >> 2;      // 4x4 tiles of 32x32
    int lx = threadIdx.x & 31, ly = threadIdx.x >> 5;   // 32x8

    if (c < 3) {
        // ---- RGB: 43x42 padded halo-5 load, vblur(window) -> 32x42, hblur -> 32x32 ----
        float* bufIn  = sm;                  // 43*42 (row 42 = scratch pad for window overrun)
        float* bufMid = sm + 43*42;          // 32 rows x 42 cols
        const int gy0 = ty*32 - 5, gx0 = tx*32 - 5;
        for (int li = ly; li < 42; li += 8) {
            int gi = gy0 + li;
            bool rowok = (gi >= 0 && gi < HW);
            {   int lj = lx;       int gj = gx0 + lj;
                bufIn[li*42 + lj] = (rowok && gj >= 0 && gj < HW) ? g_img[r][c][gi][gj] : 0.0f; }
            if (lx < 10) { int lj = lx + 32; int gj = gx0 + lj;
                bufIn[li*42 + lj] = (rowok && gj >= 0 && gj < HW) ? g_img[r][c][gi][gj] : 0.0f; }
        }
        __syncthreads();
        // vblur: thread ly owns rows [ly*4, ly*4+4), rolling window of 11
        {
            int r0 = ly * 4;
            #pragma unroll
            for (int cb = 0; cb < 2; cb++) {
                int lj = lx + cb*32;
                if (cb == 0 || lx < 10) {
                    float w[KSZ];
                    #pragma unroll
                    for (int k = 0; k < KSZ; k++) w[k] = bufIn[(r0 + k)*42 + lj];
                    #pragma unroll
                    for (int o = 0; o < 4; o++) {
                        float acc = 0.0f;
                        #pragma unroll
                        for (int k = 0; k < KSZ; k++) acc = fmaf(GW[k], w[k], acc);
                        bufMid[(r0 + o)*42 + lj] = acc;
                        #pragma unroll
                        for (int k = 0; k < KSZ-1; k++) w[k] = w[k+1];
                        w[KSZ-1] = bufIn[(r0 + o + KSZ)*42 + lj];   // row <= 42 (pad row)
                    }
                }
            }
        }
        __syncthreads();
        for (int li = ly; li < 32; li += 8) {
            float acc = 0.0f;
            #pragma unroll
            for (int k = 0; k < KSZ; k++) acc = fmaf(GW[k], bufMid[li*42 + lx + k], acc);
            out[((r*4 + c) << 14) + (ty*32 + li)*HW + tx*32 + lx] = acc;
        }
        return;
    }

    // ---- MASK: 74x74 halo-21, erode + one 21-tap V pass + one 21-tap H pass ----
    float* bufA = sm;            // 74*74 = 5476
    float* bufB = sm + 5476;
    const int gy0 = ty*32 - 21, gx0 = tx*32 - 21;
    // load raw mask, +INF outside image (erode input)
    for (int li = ly; li < 74; li += 8) {
        int gi = gy0 + li;
        bool rowok = (gi >= 0 && gi < HW);
        #pragma unroll
        for (int cb = 0; cb < 3; cb++) {
            int lj = lx + cb*32;
            if (lj < 74) {
                int gj = gx0 + lj;
                bufA[li*74 + lj] = (rowok && gj >= 0 && gj < HW) ? g_img[r][3][gi][gj] : 3.0e38f;
            }
        }
    }
    __syncthreads();
    // erode rows/cols [10,64): 3x3 min (INF pad); gate 0 outside image -> bufB
    for (int li = 10 + ly; li < 64; li += 8) {
        int gi = gy0 + li;
        #pragma unroll
        for (int cb = 0; cb < 2; cb++) {
            int lj = 10 + lx + cb*32;
            if (lj < 64) {
                int gj = gx0 + lj;
                const float* rm = bufA + (li-1)*74 + lj;
                const float* r0 = bufA + li*74 + lj;
                const float* rp = bufA + (li+1)*74 + lj;
                float m = fminf(fminf(fminf(rm[-1], rm[0]), fminf(rm[1], r0[-1])),
                                fminf(fminf(r0[0], r0[1]), fminf(fminf(rp[-1], rp[0]), rp[1])));
                bool inimg = (gi >= 0 && gi < HW && gj >= 0 && gj < HW);
                bufB[li*74 + lj] = inimg ? m : 0.0f;
            }
        }
    }
    __syncthreads();
    // V^2: 21-tap vertical, output rows [21,53), cols [10,64) -> bufA.
    // Row uniform per warp -> uniform branch between literal/table paths.
    for (int li = 21 + ly; li < 53; li += 8) {
        int gi = gy0 + li;                       // always in [0,128)
        int bi = min(min(gi, 127 - gi), 10);
        #pragma unroll
        for (int cb = 0; cb < 2; cb++) {
            int lj = 10 + lx + cb*32;
            if (lj < 64) {
                float acc = 0.0f;
                if (bi == 10) {
                    #pragma unroll
                    for (int t = 0; t < 21; t++)
                        acc = fmaf(W21[t], bufB[(li + t - 10)*74 + lj], acc);
                } else {
                    bool flip = (gi > 63);
                    const float* wr = g_w21[bi];
                    #pragma unroll
                    for (int t = 0; t < 21; t++)
                        acc = fmaf(__ldg(wr + (flip ? 20 - t : t)),
                                   bufB[(li + t - 10)*74 + lj], acc);
                }
                bufA[li*74 + lj] = acc;
            }
        }
    }
    __syncthreads();
    // H^2: 21-tap horizontal, output [21,53)^2 -> out
    for (int li = 21 + ly; li < 53; li += 8) {
        int lj = 21 + lx;
        int gj = gx0 + lj;                       // always in [0,128)
        int bj = min(min(gj, 127 - gj), 10);
        float acc = 0.0f;
        if (bj == 10) {
            #pragma unroll
            for (int t = 0; t < 21; t++)
                acc = fmaf(W21[t], bufA[li*74 + lj + t - 10], acc);
        } else {
            bool flip = (gj > 63);
            const float* wr = g_w21[bj];
            #pragma unroll
            for (int t = 0; t < 21; t++)
                acc = fmaf(__ldg(wr + (flip ? 20 - t : t)),
                           bufA[li*74 + lj + t - 10], acc);
        }
        out[((r*4 + 3) << 14) + (gy0 + li)*HW + gj] = acc;
    }
}

// ---------------- launcher ----------------
extern "C" void kernel_launch(void* const* d_in, const int* in_sizes, int n_in,
                              void* d_out, int out_size) {
    const float* vertices  = (const float*)d_in[0];
    const float* quat      = (const float*)d_in[1];
    const float* trans     = (const float*)d_in[2];
    const float* face_ff   = (const float*)d_in[4];
    const float* tex       = (const float*)d_in[5];
    const int*   faces     = (const int*)d_in[6];
    float* out = (float*)d_out;

    static bool attr_set = false;
    if (!attr_set) {
        cudaFuncSetAttribute(raster_kernel, cudaFuncAttributeMaxDynamicSharedMemorySize, 49152);
        cudaFuncSetAttribute(post_kernel,   cudaFuncAttributeMaxDynamicSharedMemorySize, 45056);
        attr_set = true;
    }

    rot_kernel<<<1, 32>>>(quat, trans);
    face_kernel<<<dim3(4, NRENDER), 256>>>(vertices, faces, face_ff);
    raster_kernel<<<dim3(64, NRENDER), 256, 49152>>>(tex);
    post_kernel<<<dim3(16, NRENDER, 4), 256, 45056>>>(out);
}

// round 10
// speedup vs baseline: 1.2106x; 1.0123x over previous
#include <cuda_runtime.h>
#include <math.h>

#define NRENDER 16        // NF(2) * T(8)
#define NFACE_C 1024
#define HW 128
#define TEXW 256
#define KSZ 11

// ---------------- device scratch ----------------
__device__ float g_RT[NRENDER][12];             // 9 rotation + 3 translation
__device__ float g_plane[NRENDER][NFACE_C][16]; // A0,B0,C0,A1,B1,C1,A2,B2,C2,zA,zB,zC,xmin,xmax,ymin,ymax
__device__ float g_uvp[NRENDER][NFACE_C][8];    // uA,uB,uC,vA,vB,vC,pad,pad
__device__ float g_img[NRENDER][4][HW][HW];     // rgb + raw mask
__device__ float g_w21[11][21];                 // border-corrected composed blur weights

// 11-tap gaussian literals (sigma=1), center at index 5
#define GW0 1.4867195147e-06f
#define GW1 1.3383022576e-04f
#define GW2 4.4318484119e-03f
#define GW3 5.3990966513e-02f
#define GW4 2.4197072452e-01f
#define GW5 3.9894228040e-01f

__device__ __forceinline__ unsigned fkey(float f) {
    unsigned u = __float_as_uint(f);
    return u ^ ((u & 0x80000000u) ? 0xFFFFFFFFu : 0x80000000u);
}

// ---------------- quaternion helper ----------------
__device__ __forceinline__ void quat_to_R_dev(const float* q, float scale, float* R) {
    float c = q[0], x = q[1], y = q[2], z = q[3];
    float sin2 = x*x + y*y + z*z;
    float sint = sqrtf(fmaxf(sin2, 1e-12f));
    float tt = 2.0f * ((c < 0.0f) ? atan2f(-sint, -c) : atan2f(sint, c));
    float k = (sin2 > 1e-12f) ? (tt / sint) : 2.0f;
    float ax = k*x*scale, ay = k*y*scale, az = k*z*scale;
    float th = sqrtf(ax*ax + ay*ay + az*az);
    float inv = 1.0f / fmaxf(th, 1e-8f);
    float ux = ax*inv, uy = ay*inv, uz = az*inv;
    float s = sinf(th), co = cosf(th), oc = 1.0f - co;
    R[0] = 1.0f + oc*(-(uy*uy + uz*uz));
    R[1] = -s*uz + oc*(ux*uy);
    R[2] =  s*uy + oc*(ux*uz);
    R[3] =  s*uz + oc*(ux*uy);
    R[4] = 1.0f + oc*(-(ux*ux + uz*uz));
    R[5] = -s*ux + oc*(uy*uz);
    R[6] = -s*uy + oc*(ux*uz);
    R[7] =  s*ux + oc*(uy*uz);
    R[8] = 1.0f + oc*(-(ux*ux + uy*uy));
}

// ---------------- rotation chains + border weight table ----------------
__global__ void rot_kernel(const float* __restrict__ quat, const float* __restrict__ trans) {
    int r = threadIdx.x;
    if (r < NRENDER) {
        int f = r >> 3, t = r & 7;
        float R0[9], Rs[9];
        quat_to_R_dev(&quat[f*8 + 4], 1.0f, R0);     // q[:,f,1]
        quat_to_R_dev(&quat[f*8 + 0], 0.125f, Rs);   // q[:,f,0]/T/ROT_DIV
        float Rm[9];
        #pragma unroll
        for (int k = 0; k < 9; k++) Rm[k] = R0[k];
        for (int s = 0; s < t; s++) {
            float Nw[9];
            #pragma unroll
            for (int i = 0; i < 3; i++)
                #pragma unroll
                for (int k = 0; k < 3; k++)
                    Nw[i*3+k] = Rm[i*3+0]*Rs[0*3+k] + Rm[i*3+1]*Rs[1*3+k] + Rm[i*3+2]*Rs[2*3+k];
            #pragma unroll
            for (int k = 0; k < 9; k++) Rm[k] = Nw[k];
        }
        #pragma unroll
        for (int k = 0; k < 9; k++) g_RT[r][k] = Rm[k];
        float ti = (float)t / 7.0f;
        #pragma unroll
        for (int a = 0; a < 3; a++)
            g_RT[r][9+a] = trans[a*4 + f*2 + 1] + ti * trans[a*4 + f*2 + 0];
    }
    // composed-blur weight rows for image-border outputs (see round-9 notes)
    int b = threadIdx.x - NRENDER;
    if (b >= 0 && b < 11) {
        const float g[KSZ] = {GW0,GW1,GW2,GW3,GW4,GW5,GW4,GW3,GW2,GW1,GW0};
        for (int t = 0; t < 21; t++) {
            int j = b + t - 10;
            float w = 0.0f;
            if (j >= 0) {
                int kmin = max(0, max(b-5, j-5));
                int kmax = min(b+5, j+5);
                for (int k = kmin; k <= kmax; k++)
                    w += g[k-b+5] * g[j-k+5];
            }
            g_w21[b][t] = w;
        }
    }
}

// ---------------- per (render, face) plane setup ----------------
// grid (4, NRENDER), block 256
__global__ void face_kernel(const float* __restrict__ verts, const int* __restrict__ faces,
                            const float* __restrict__ ff) {
    int r = blockIdx.y;
    int fc = blockIdx.x * 256 + threadIdx.x;
    float R[12];
    #pragma unroll
    for (int k = 0; k < 12; k++) R[k] = __ldg(&g_RT[r][k]);
    const float invt = 1.0f / tanf(0.3925f);   // 1/tan(FOV/2); px==py since W==H
    float sx[3], sy[3], zz[3], P[3][3];
    #pragma unroll
    for (int k = 0; k < 3; k++) {
        int vi = faces[fc*3 + k];
        float vx = verts[vi*3+0], vy = verts[vi*3+1], vz = verts[vi*3+2];
        float Xc = R[0]*vx + R[1]*vy + R[2]*vz + R[9];
        float Yc = R[3]*vx + R[4]*vy + R[5]*vz + R[10];
        float Zc = R[6]*vx + R[7]*vy + R[8]*vz + R[11] - 2.0f;   // CAM_D
        P[k][0] = Xc; P[k][1] = Yc; P[k][2] = Zc;
        float invnz = 1.0f / (-Zc);
        sx[k] = (Xc * invt) * invnz;
        sy[k] = (Yc * invt) * invnz;
        zz[k] = Zc;
    }
    float e1x = P[1][0]-P[0][0], e1y = P[1][1]-P[0][1], e1z = P[1][2]-P[0][2];
    float e2x = P[2][0]-P[0][0], e2y = P[2][1]-P[0][1], e2z = P[2][2]-P[0][2];
    float nx = e1y*e2z - e1z*e2y;
    float ny = e1z*e2x - e1x*e2z;
    float nzv = e1x*e2y - e1y*e2x;
    float nz = nzv / (sqrtf(nx*nx + ny*ny + nzv*nzv) + 1e-8f);

    float area = (sx[1]-sx[0])*(sy[2]-sy[0]) - (sy[1]-sy[0])*(sx[2]-sx[0]);
    if (fabsf(area) < 1e-10f) area = 1e-10f;
    float ia = 1.0f / area;
    float A0 = -(sy[2]-sy[1])*ia, B0 = (sx[2]-sx[1])*ia;
    float C0 = ((sy[2]-sy[1])*sx[1] - (sx[2]-sx[1])*sy[1])*ia;
    float A1 = -(sy[0]-sy[2])*ia, B1 = (sx[0]-sx[2])*ia;
    float C1 = ((sy[0]-sy[2])*sx[2] - (sx[0]-sx[2])*sy[2])*ia;
    float A2 = -(sy[1]-sy[0])*ia, B2 = (sx[1]-sx[0])*ia;
    float C2 = ((sy[1]-sy[0])*sx[0] - (sx[1]-sx[0])*sy[0])*ia;
    float zA = A0*zz[0] + A1*zz[1] + A2*zz[2];
    float zB = B0*zz[0] + B1*zz[1] + B2*zz[2];
    float zC = C0*zz[0] + C1*zz[1] + C2*zz[2];

    float xmin, xmax, ymin, ymax;
    if (nz > 0.0f) {
        xmin = fminf(sx[0], fminf(sx[1], sx[2]));
        xmax = fmaxf(sx[0], fmaxf(sx[1], sx[2]));
        ymin = fminf(sy[0], fminf(sy[1], sy[2]));
        ymax = fmaxf(sy[0], fmaxf(sy[1], sy[2]));
    } else {
        xmin = 1e30f; xmax = -1e30f; ymin = 1e30f; ymax = -1e30f;  // never passes cull
    }
    float* pl = g_plane[r][fc];
    pl[0]=A0; pl[1]=B0; pl[2]=C0; pl[3]=A1; pl[4]=B1; pl[5]=C1;
    pl[6]=A2; pl[7]=B2; pl[8]=C2; pl[9]=zA; pl[10]=zB; pl[11]=zC;
    pl[12]=xmin; pl[13]=xmax; pl[14]=ymin; pl[15]=ymax;

    float u0 = ff[fc*6+0], v0 = ff[fc*6+1];
    float u1 = ff[fc*6+2], v1 = ff[fc*6+3];
    float u2 = ff[fc*6+4], v2 = ff[fc*6+5];
    float* up = g_uvp[r][fc];
    up[0] = A0*u0 + A1*u1 + A2*u2;
    up[1] = B0*u0 + B1*u1 + B2*u2;
    up[2] = C0*u0 + C1*u1 + C2*u2;
    up[3] = A0*v0 + A1*v1 + A2*v2;
    up[4] = B0*v0 + B1*v1 + B2*v2;
    up[5] = C0*v0 + C1*v1 + C2*v2;
}

// ---------------- rasterize + texture sample ----------------
// grid: (64 tiles, 16 renders), block 256 = 16x16 px (1 px/thread), 48KB dynamic.
// NEW: per-lane depth cull — skip faces whose tile-corner zmax key is strictly
// below this lane's running best-z key (exact: strict losers only).
__global__ void __launch_bounds__(256) raster_kernel(const float* __restrict__ tex) {
    extern __shared__ float sm[];         // 12288 floats = 48KB
    __shared__ unsigned s_key[NFACE_C];   // zmax keys: partial at [p], full at [1023-p]
    __shared__ int s_fid[NFACE_C];        // face ids, same layout
    __shared__ int s_np, s_nf;
    __shared__ unsigned s_M;
    int r = blockIdx.y;
    int tile = blockIdx.x;
    int tx = tile & 7, ty = tile >> 3;
    int lj = threadIdx.x & 15, li = threadIdx.x >> 4;
    int j = tx*16 + lj, i = ty*16 + li;
    const float step = 2.0f / 127.0f;
    float X = -1.0f + (float)j * step;
    float Y =  1.0f - (float)i * step;
    float tX0 = -1.0f + (float)(tx*16) * step;
    float tX1 = -1.0f + (float)(tx*16 + 15) * step;
    float tY0 =  1.0f - (float)(ty*16) * step;
    float tY1 =  1.0f - (float)(ty*16 + 15) * step;

    if (threadIdx.x == 0) { s_np = 0; s_nf = 0; s_M = 0u; }
    __syncthreads();

    for (int fc = threadIdx.x; fc < NFACE_C; fc += 256) {
        const float* pl = g_plane[r][fc];
        float4 bb = *(const float4*)(pl + 12);
        if (!(bb.x <= tX1 && bb.y >= tX0 && bb.z <= tY0 && bb.w >= tY1)) continue;
        float4 a = *(const float4*)(pl + 0);
        float4 b = *(const float4*)(pl + 4);
        float4 c = *(const float4*)(pl + 8);
        bool reject = false, full = true;
        {
            float A[3] = {a.x, a.w, b.z}, Bc[3] = {a.y, b.x, b.w}, Cc[3] = {a.z, b.y, c.x};
            #pragma unroll
            for (int e = 0; e < 3; e++) {
                float e00 = fmaf(A[e], tX0, fmaf(Bc[e], tY0, Cc[e]));
                float e01 = fmaf(A[e], tX1, fmaf(Bc[e], tY0, Cc[e]));
                float e10 = fmaf(A[e], tX0, fmaf(Bc[e], tY1, Cc[e]));
                float e11 = fmaf(A[e], tX1, fmaf(Bc[e], tY1, Cc[e]));
                float mn = fminf(fminf(e00, e01), fminf(e10, e11));
                float mx = fmaxf(fmaxf(e00, e01), fmaxf(e10, e11));
                if (mx < 0.0f) reject = true;
                if (mn < 0.0f) full = false;
            }
        }
        if (reject) continue;
        float z00 = fmaf(c.y, tX0, fmaf(c.z, tY0, c.w));
        float z01 = fmaf(c.y, tX1, fmaf(c.z, tY0, c.w));
        float z10 = fmaf(c.y, tX0, fmaf(c.z, tY1, c.w));
        float z11 = fmaf(c.y, tX1, fmaf(c.z, tY1, c.w));
        float zmx = fmaxf(fmaxf(z00, z01), fmaxf(z10, z11));
        if (full) {
            float zmn = fminf(fminf(z00, z01), fminf(z10, z11));
            atomicMax(&s_M, fkey(zmn - 1e-6f));
            int p = atomicAdd(&s_nf, 1);
            float* d = sm + 12288 - 4*(p+1);
            d[0] = c.y; d[1] = c.z; d[2] = c.w;
            s_fid[1023 - p] = fc;
            s_key[1023 - p] = fkey(zmx);
        } else {
            int p = atomicAdd(&s_np, 1);
            float* d = sm + p*12;
            *(float4*)(d + 0) = a;
            *(float4*)(d + 4) = b;
            *(float4*)(d + 8) = c;
            s_fid[p] = fc;
            s_key[p] = fkey(zmx);
        }
    }
    __syncthreads();
    int np = s_np, nf = s_nf;
    unsigned M = s_M;

    float    best_z  = -3.0e38f;
    int      best_f  = 0x7fffffff;
    unsigned bestkey = 0u;                // no cull until first update
    int      hit_i   = (nf > 0) ? 1 : 0;

    // full-cover faces: block M prune + per-lane running cull
    for (int q = 0; q < nf; q++) {
        unsigned key = s_key[1023 - q];
        if (key < M || key < bestkey) continue;
        const float4 zr = *(const float4*)(sm + 12288 - 4*(q+1));
        float z = fmaf(zr.x, X, fmaf(zr.y, Y, zr.z));
        int fid = s_fid[1023 - q];
        if (z > best_z) { best_z = z; best_f = fid; bestkey = fkey(z); }
        else if (z == best_z && fid < best_f) { best_f = fid; }
    }
    // partial faces: per-lane running cull (strictly dominates M here)
    for (int q = 0; q < np; q++) {
        if (s_key[q] < bestkey) continue;
        const float* d = sm + q*12;
        float4 a = *(const float4*)(d + 0);
        float4 b = *(const float4*)(d + 4);
        float4 c = *(const float4*)(d + 8);
        int fid = s_fid[q];
        float b0 = fmaf(a.x, X, fmaf(a.y, Y, a.z));
        float b1 = fmaf(a.w, X, fmaf(b.x, Y, b.y));
        float b2 = fmaf(b.z, X, fmaf(b.w, Y, c.x));
        float z  = fmaf(c.y, X, fmaf(c.z, Y, c.w));
        if (fminf(b0, fminf(b1, b2)) >= 0.0f) {
            hit_i = 1;
            if (z > best_z) { best_z = z; best_f = fid; bestkey = fkey(z); }
            else if (z == best_z && fid < best_f) { best_f = fid; }
        }
    }

    float u = 0.0f, v = 0.0f;
    if (hit_i) {
        const float* up = g_uvp[r][best_f];
        u = fmaf(up[0], X, fmaf(up[1], Y, up[2]));
        v = fmaf(up[3], X, fmaf(up[4], Y, up[5]));
    }
    float xf = u * 255.0f;
    float yf = (1.0f - v) * 255.0f;
    float x0 = fminf(fmaxf(floorf(xf), 0.0f), 254.0f);
    float y0 = fminf(fmaxf(floorf(yf), 0.0f), 254.0f);
    float fx = xf - x0, fy = yf - y0;
    int xi = (int)x0, yi = (int)y0;
    int base = yi * TEXW + xi;
    #pragma unroll
    for (int cch = 0; cch < 3; cch++) {
        const float* tc = tex + cch * (TEXW*TEXW);
        float t00 = __ldg(tc + base);
        float t01 = __ldg(tc + base + 1);
        float t10 = __ldg(tc + base + TEXW);
        float t11 = __ldg(tc + base + TEXW + 1);
        float val = t00*(1.0f-fx)*(1.0f-fy) + t01*fx*(1.0f-fy)
                  + t10*(1.0f-fx)*fy        + t11*fx*fy;
        g_img[r][cch][i][j] = val;
    }
    g_img[r][3][i][j] = (float)hit_i;
}

// ---------------- tiled fused epilogue ----------------
// grid (16 tiles, NRENDER, 4), block 256 as 32x8.
// z=0 -> MASK (long pole, launched FIRST); z=1..3 -> RGB.
// Mask double-blur collapsed to ONE 21-tap pass per axis (V^2 then H^2);
// image-border outputs use exact clip-corrected weights from g_w21.
__global__ void __launch_bounds__(256) post_kernel(float* __restrict__ out) {
    extern __shared__ float sm[];
    const float GW[KSZ] = {GW0,GW1,GW2,GW3,GW4,GW5,GW4,GW3,GW2,GW1,GW0};
    const float W21[21] = {
        2.2103349e-12f, 3.9795740e-10f, 3.1088500e-08f, 1.3467706e-06f,
        3.4812100e-05f, 5.4450606e-04f, 5.1673262e-03f, 2.9729460e-02f,
        1.0378766e-01f, 2.1967292e-01f, 2.8212397e-01f, 2.1967292e-01f,
        1.0378766e-01f, 2.9729460e-02f, 5.1673262e-03f, 5.4450606e-04f,
        3.4812100e-05f, 1.3467706e-06f, 3.1088500e-08f, 3.9795740e-10f,
        2.2103349e-12f };
    int tile = blockIdx.x, r = blockIdx.y;
    int c = (blockIdx.z + 3) & 3;           // z=0 -> c=3 (mask first)
    int tx = tile & 3, ty = tile >> 2;      // 4x4 tiles of 32x32
    int lx = threadIdx.x & 31, ly = threadIdx.x >> 5;   // 32x8

    if (c < 3) {
        // ---- RGB: 43x42 padded halo-5 load, vblur(window) -> 32x42, hblur -> 32x32 ----
        float* bufIn  = sm;                  // 43*42 (row 42 = scratch pad)
        float* bufMid = sm + 43*42;          // 32 rows x 42 cols
        const int gy0 = ty*32 - 5, gx0 = tx*32 - 5;
        for (int li = ly; li < 42; li += 8) {
            int gi = gy0 + li;
            bool rowok = (gi >= 0 && gi < HW);
            {   int lj = lx;       int gj = gx0 + lj;
                bufIn[li*42 + lj] = (rowok && gj >= 0 && gj < HW) ? g_img[r][c][gi][gj] : 0.0f; }
            if (lx < 10) { int lj = lx + 32; int gj = gx0 + lj;
                bufIn[li*42 + lj] = (rowok && gj >= 0 && gj < HW) ? g_img[r][c][gi][gj] : 0.0f; }
        }
        __syncthreads();
        {
            int r0 = ly * 4;
            #pragma unroll
            for (int cb = 0; cb < 2; cb++) {
                int lj = lx + cb*32;
                if (cb == 0 || lx < 10) {
                    float w[KSZ];
                    #pragma unroll
                    for (int k = 0; k < KSZ; k++) w[k] = bufIn[(r0 + k)*42 + lj];
                    #pragma unroll
                    for (int o = 0; o < 4; o++) {
                        float acc = 0.0f;
                        #pragma unroll
                        for (int k = 0; k < KSZ; k++) acc = fmaf(GW[k], w[k], acc);
                        bufMid[(r0 + o)*42 + lj] = acc;
                        #pragma unroll
                        for (int k = 0; k < KSZ-1; k++) w[k] = w[k+1];
                        w[KSZ-1] = bufIn[(r0 + o + KSZ)*42 + lj];
                    }
                }
            }
        }
        __syncthreads();
        for (int li = ly; li < 32; li += 8) {
            float acc = 0.0f;
            #pragma unroll
            for (int k = 0; k < KSZ; k++) acc = fmaf(GW[k], bufMid[li*42 + lx + k], acc);
            out[((r*4 + c) << 14) + (ty*32 + li)*HW + tx*32 + lx] = acc;
        }
        return;
    }

    // ---- MASK: 74x74 halo-21, erode + one 21-tap V pass + one 21-tap H pass ----
    float* bufA = sm;            // 74*74 = 5476
    float* bufB = sm + 5476;
    const int gy0 = ty*32 - 21, gx0 = tx*32 - 21;
    for (int li = ly; li < 74; li += 8) {
        int gi = gy0 + li;
        bool rowok = (gi >= 0 && gi < HW);
        #pragma unroll
        for (int cb = 0; cb < 3; cb++) {
            int lj = lx + cb*32;
            if (lj < 74) {
                int gj = gx0 + lj;
                bufA[li*74 + lj] = (rowok && gj >= 0 && gj < HW) ? g_img[r][3][gi][gj] : 3.0e38f;
            }
        }
    }
    __syncthreads();
    for (int li = 10 + ly; li < 64; li += 8) {
        int gi = gy0 + li;
        #pragma unroll
        for (int cb = 0; cb < 2; cb++) {
            int lj = 10 + lx + cb*32;
            if (lj < 64) {
                int gj = gx0 + lj;
                const float* rm = bufA + (li-1)*74 + lj;
                const float* r0 = bufA + li*74 + lj;
                const float* rp = bufA + (li+1)*74 + lj;
                float m = fminf(fminf(fminf(rm[-1], rm[0]), fminf(rm[1], r0[-1])),
                                fminf(fminf(r0[0], r0[1]), fminf(fminf(rp[-1], rp[0]), rp[1])));
                bool inimg = (gi >= 0 && gi < HW && gj >= 0 && gj < HW);
                bufB[li*74 + lj] = inimg ? m : 0.0f;
            }
        }
    }
    __syncthreads();
    for (int li = 21 + ly; li < 53; li += 8) {
        int gi = gy0 + li;
        int bi = min(min(gi, 127 - gi), 10);
        #pragma unroll
        for (int cb = 0; cb < 2; cb++) {
            int lj = 10 + lx + cb*32;
            if (lj < 64) {
                float acc = 0.0f;
                if (bi == 10) {
                    #pragma unroll
                    for (int t = 0; t < 21; t++)
                        acc = fmaf(W21[t], bufB[(li + t - 10)*74 + lj], acc);
                } else {
                    bool flip = (gi > 63);
                    const float* wr = g_w21[bi];
                    #pragma unroll
                    for (int t = 0; t < 21; t++)
                        acc = fmaf(__ldg(wr + (flip ? 20 - t : t)),
                                   bufB[(li + t - 10)*74 + lj], acc);
                }
                bufA[li*74 + lj] = acc;
            }
        }
    }
    __syncthreads();
    for (int li = 21 + ly; li < 53; li += 8) {
        int lj = 21 + lx;
        int gj = gx0 + lj;
        int bj = min(min(gj, 127 - gj), 10);
        float acc = 0.0f;
        if (bj == 10) {
            #pragma unroll
            for (int t = 0; t < 21; t++)
                acc = fmaf(W21[t], bufA[li*74 + lj + t - 10], acc);
        } else {
            bool flip = (gj > 63);
            const float* wr = g_w21[bj];
            #pragma unroll
            for (int t = 0; t < 21; t++)
                acc = fmaf(__ldg(wr + (flip ? 20 - t : t)),
                           bufA[li*74 + lj + t - 10], acc);
        }
        out[((r*4 + 3) << 14) + (gy0 + li)*HW + gj] = acc;
    }
}

// ---------------- launcher ----------------
extern "C" void kernel_launch(void* const* d_in, const int* in_sizes, int n_in,
                              void* d_out, int out_size) {
    const float* vertices  = (const float*)d_in[0];
    const float* quat      = (const float*)d_in[1];
    const float* trans     = (const float*)d_in[2];
    const float* face_ff   = (const float*)d_in[4];
    const float* tex       = (const float*)d_in[5];
    const int*   faces     = (const int*)d_in[6];
    float* out = (float*)d_out;

    static bool attr_set = false;
    if (!attr_set) {
        cudaFuncSetAttribute(raster_kernel, cudaFuncAttributeMaxDynamicSharedMemorySize, 49152);
        cudaFuncSetAttribute(post_kernel,   cudaFuncAttributeMaxDynamicSharedMemorySize, 45056);
        attr_set = true;
    }

    rot_kernel<<<1, 32>>>(quat, trans);
    face_kernel<<<dim3(4, NRENDER), 256>>>(vertices, faces, face_ff);
    raster_kernel<<<dim3(64, NRENDER), 256, 49152>>>(tex);
    post_kernel<<<dim3(16, NRENDER, 4), 256, 45056>>>(out);
}

// round 11
// speedup vs baseline: 1.4172x; 1.1706x over previous
#include <cuda_runtime.h>
#include <math.h>

#define NRENDER 16        // NF(2) * T(8)
#define NFACE_C 1024
#define HW 128
#define TEXW 256
#define KSZ 11

// ---------------- device scratch ----------------
__device__ float4 g_plane4[NRENDER][NFACE_C][3]; // {A0,B0,C0,A1},{B1,C1,A2,B2},{C2,zA,zB,zC}
__device__ float4 g_bbox[NRENDER][NFACE_C];      // xmin,xmax,ymin,ymax (dense scan stream)
__device__ float  g_uvp[NRENDER][NFACE_C][8];    // uA,uB,uC,vA,vB,vC,pad,pad
__device__ float  g_img[NRENDER][4][HW][HW];     // rgb + raw mask

// 11-tap gaussian literals (sigma=1), center at index 5
#define GW0 1.4867195147e-06f
#define GW1 1.3383022576e-04f
#define GW2 4.4318484119e-03f
#define GW3 5.3990966513e-02f
#define GW4 2.4197072452e-01f
#define GW5 3.9894228040e-01f

__device__ __forceinline__ unsigned fkey(float f) {
    unsigned u = __float_as_uint(f);
    return u ^ ((u & 0x80000000u) ? 0xFFFFFFFFu : 0x80000000u);
}

// ---------------- quaternion helper ----------------
__device__ __forceinline__ void quat_to_R_dev(const float* q, float scale, float* R) {
    float c = q[0], x = q[1], y = q[2], z = q[3];
    float sin2 = x*x + y*y + z*z;
    float sint = sqrtf(fmaxf(sin2, 1e-12f));
    float tt = 2.0f * ((c < 0.0f) ? atan2f(-sint, -c) : atan2f(sint, c));
    float k = (sin2 > 1e-12f) ? (tt / sint) : 2.0f;
    float ax = k*x*scale, ay = k*y*scale, az = k*z*scale;
    float th = sqrtf(ax*ax + ay*ay + az*az);
    float inv = 1.0f / fmaxf(th, 1e-8f);
    float ux = ax*inv, uy = ay*inv, uz = az*inv;
    float s = sinf(th), co = cosf(th), oc = 1.0f - co;
    R[0] = 1.0f + oc*(-(uy*uy + uz*uz));
    R[1] = -s*uz + oc*(ux*uy);
    R[2] =  s*uy + oc*(ux*uz);
    R[3] =  s*uz + oc*(ux*uy);
    R[4] = 1.0f + oc*(-(ux*ux + uz*uz));
    R[5] = -s*ux + oc*(uy*uz);
    R[6] = -s*uy + oc*(ux*uz);
    R[7] =  s*ux + oc*(uy*uz);
    R[8] = 1.0f + oc*(-(ux*ux + uy*uy));
}

// ---------------- per (render, face) plane setup (rot chain fused, per-thread) ----------------
// grid (4, NRENDER), block 256
__global__ void face_kernel(const float* __restrict__ verts, const int* __restrict__ faces,
                            const float* __restrict__ ff,
                            const float* __restrict__ quat, const float* __restrict__ trans) {
    int r = blockIdx.y;
    int fc = blockIdx.x * 256 + threadIdx.x;
    // every thread computes the (identical) rotation chain for this render —
    // fully parallel, no serialization, ~500 flops
    int f = r >> 3, t = r & 7;
    float R[12];
    {
        float R0[9], Rs[9];
        quat_to_R_dev(&quat[f*8 + 4], 1.0f, R0);     // q[:,f,1]
        quat_to_R_dev(&quat[f*8 + 0], 0.125f, Rs);   // q[:,f,0]/T/ROT_DIV
        float Rm[9];
        #pragma unroll
        for (int k = 0; k < 9; k++) Rm[k] = R0[k];
        for (int s = 0; s < t; s++) {
            float Nw[9];
            #pragma unroll
            for (int i = 0; i < 3; i++)
                #pragma unroll
                for (int k = 0; k < 3; k++)
                    Nw[i*3+k] = Rm[i*3+0]*Rs[0*3+k] + Rm[i*3+1]*Rs[1*3+k] + Rm[i*3+2]*Rs[2*3+k];
            #pragma unroll
            for (int k = 0; k < 9; k++) Rm[k] = Nw[k];
        }
        #pragma unroll
        for (int k = 0; k < 9; k++) R[k] = Rm[k];
        float ti = (float)t / 7.0f;
        #pragma unroll
        for (int a = 0; a < 3; a++)
            R[9+a] = trans[a*4 + f*2 + 1] + ti * trans[a*4 + f*2 + 0];
    }
    const float invt = 1.0f / tanf(0.3925f);   // 1/tan(FOV/2); px==py since W==H
    float sx[3], sy[3], zz[3], P[3][3];
    #pragma unroll
    for (int k = 0; k < 3; k++) {
        int vi = faces[fc*3 + k];
        float vx = verts[vi*3+0], vy = verts[vi*3+1], vz = verts[vi*3+2];
        float Xc = R[0]*vx + R[1]*vy + R[2]*vz + R[9];
        float Yc = R[3]*vx + R[4]*vy + R[5]*vz + R[10];
        float Zc = R[6]*vx + R[7]*vy + R[8]*vz + R[11] - 2.0f;   // CAM_D
        P[k][0] = Xc; P[k][1] = Yc; P[k][2] = Zc;
        float invnz = 1.0f / (-Zc);
        sx[k] = (Xc * invt) * invnz;
        sy[k] = (Yc * invt) * invnz;
        zz[k] = Zc;
    }
    float e1x = P[1][0]-P[0][0], e1y = P[1][1]-P[0][1], e1z = P[1][2]-P[0][2];
    float e2x = P[2][0]-P[0][0], e2y = P[2][1]-P[0][1], e2z = P[2][2]-P[0][2];
    float nx = e1y*e2z - e1z*e2y;
    float ny = e1z*e2x - e1x*e2z;
    float nzv = e1x*e2y - e1y*e2x;
    float nz = nzv / (sqrtf(nx*nx + ny*ny + nzv*nzv) + 1e-8f);

    float area = (sx[1]-sx[0])*(sy[2]-sy[0]) - (sy[1]-sy[0])*(sx[2]-sx[0]);
    if (fabsf(area) < 1e-10f) area = 1e-10f;
    float ia = 1.0f / area;
    float A0 = -(sy[2]-sy[1])*ia, B0 = (sx[2]-sx[1])*ia;
    float C0 = ((sy[2]-sy[1])*sx[1] - (sx[2]-sx[1])*sy[1])*ia;
    float A1 = -(sy[0]-sy[2])*ia, B1 = (sx[0]-sx[2])*ia;
    float C1 = ((sy[0]-sy[2])*sx[2] - (sx[0]-sx[2])*sy[2])*ia;
    float A2 = -(sy[1]-sy[0])*ia, B2 = (sx[1]-sx[0])*ia;
    float C2 = ((sy[1]-sy[0])*sx[0] - (sx[1]-sx[0])*sy[0])*ia;
    float zA = A0*zz[0] + A1*zz[1] + A2*zz[2];
    float zB = B0*zz[0] + B1*zz[1] + B2*zz[2];
    float zC = C0*zz[0] + C1*zz[1] + C2*zz[2];

    float xmin, xmax, ymin, ymax;
    if (nz > 0.0f) {
        xmin = fminf(sx[0], fminf(sx[1], sx[2]));
        xmax = fmaxf(sx[0], fmaxf(sx[1], sx[2]));
        ymin = fminf(sy[0], fminf(sy[1], sy[2]));
        ymax = fmaxf(sy[0], fmaxf(sy[1], sy[2]));
    } else {
        xmin = 1e30f; xmax = -1e30f; ymin = 1e30f; ymax = -1e30f;  // never passes cull
    }
    g_plane4[r][fc][0] = make_float4(A0, B0, C0, A1);
    g_plane4[r][fc][1] = make_float4(B1, C1, A2, B2);
    g_plane4[r][fc][2] = make_float4(C2, zA, zB, zC);
    g_bbox[r][fc]      = make_float4(xmin, xmax, ymin, ymax);

    float u0 = ff[fc*6+0], v0 = ff[fc*6+1];
    float u1 = ff[fc*6+2], v1 = ff[fc*6+3];
    float u2 = ff[fc*6+4], v2 = ff[fc*6+5];
    float* up = g_uvp[r][fc];
    up[0] = A0*u0 + A1*u1 + A2*u2;
    up[1] = B0*u0 + B1*u1 + B2*u2;
    up[2] = C0*u0 + C1*u1 + C2*u2;
    up[3] = A0*v0 + A1*v1 + A2*v2;
    up[4] = B0*v0 + B1*v1 + B2*v2;
    up[5] = C0*v0 + C1*v1 + C2*v2;
}

// ---------------- rasterize + texture sample ----------------
// grid: (64 tiles, 16 renders), block 256 = 16x16 px (1 px/thread), 48KB dynamic.
// Dense-bbox compaction scan; block M cull + per-lane running depth cull.
__global__ void __launch_bounds__(256) raster_kernel(const float* __restrict__ tex) {
    extern __shared__ float sm[];         // 12288 floats = 48KB
    __shared__ unsigned s_key[NFACE_C];   // zmax keys: partial at [p], full at [1023-p]
    __shared__ int s_fid[NFACE_C];        // face ids, same layout
    __shared__ int s_np, s_nf;
    __shared__ unsigned s_M;
    int r = blockIdx.y;
    int tile = blockIdx.x;
    int tx = tile & 7, ty = tile >> 3;
    int lj = threadIdx.x & 15, li = threadIdx.x >> 4;
    int j = tx*16 + lj, i = ty*16 + li;
    const float step = 2.0f / 127.0f;
    float X = -1.0f + (float)j * step;
    float Y =  1.0f - (float)i * step;
    float tX0 = -1.0f + (float)(tx*16) * step;
    float tX1 = -1.0f + (float)(tx*16 + 15) * step;
    float tY0 =  1.0f - (float)(ty*16) * step;
    float tY1 =  1.0f - (float)(ty*16 + 15) * step;

    if (threadIdx.x == 0) { s_np = 0; s_nf = 0; s_M = 0u; }
    __syncthreads();

    for (int fc = threadIdx.x; fc < NFACE_C; fc += 256) {
        float4 bb = g_bbox[r][fc];
        if (!(bb.x <= tX1 && bb.y >= tX0 && bb.z <= tY0 && bb.w >= tY1)) continue;
        float4 a = g_plane4[r][fc][0];
        float4 b = g_plane4[r][fc][1];
        float4 c = g_plane4[r][fc][2];
        bool reject = false, full = true;
        {
            float A[3] = {a.x, a.w, b.z}, Bc[3] = {a.y, b.x, b.w}, Cc[3] = {a.z, b.y, c.x};
            #pragma unroll
            for (int e = 0; e < 3; e++) {
                float e00 = fmaf(A[e], tX0, fmaf(Bc[e], tY0, Cc[e]));
                float e01 = fmaf(A[e], tX1, fmaf(Bc[e], tY0, Cc[e]));
                float e10 = fmaf(A[e], tX0, fmaf(Bc[e], tY1, Cc[e]));
                float e11 = fmaf(A[e], tX1, fmaf(Bc[e], tY1, Cc[e]));
                float mn = fminf(fminf(e00, e01), fminf(e10, e11));
                float mx = fmaxf(fmaxf(e00, e01), fmaxf(e10, e11));
                if (mx < 0.0f) reject = true;
                if (mn < 0.0f) full = false;
            }
        }
        if (reject) continue;
        float z00 = fmaf(c.z, tX0, fmaf(c.w, tY0, 0.0f));   // placeholder, replaced below
        // z-plane coefficients are (zA,zB,zC) = (c.y, c.z, c.w)
        z00 = fmaf(c.y, tX0, fmaf(c.z, tY0, c.w));
        float z01 = fmaf(c.y, tX1, fmaf(c.z, tY0, c.w));
        float z10 = fmaf(c.y, tX0, fmaf(c.z, tY1, c.w));
        float z11 = fmaf(c.y, tX1, fmaf(c.z, tY1, c.w));
        float zmx = fmaxf(fmaxf(z00, z01), fmaxf(z10, z11));
        if (full) {
            float zmn = fminf(fminf(z00, z01), fminf(z10, z11));
            atomicMax(&s_M, fkey(zmn - 1e-6f));
            int p = atomicAdd(&s_nf, 1);
            float* d = sm + 12288 - 4*(p+1);
            d[0] = c.y; d[1] = c.z; d[2] = c.w;
            s_fid[1023 - p] = fc;
            s_key[1023 - p] = fkey(zmx);
        } else {
            int p = atomicAdd(&s_np, 1);
            float* d = sm + p*12;
            *(float4*)(d + 0) = a;
            *(float4*)(d + 4) = b;
            *(float4*)(d + 8) = c;
            s_fid[p] = fc;
            s_key[p] = fkey(zmx);
        }
    }
    __syncthreads();
    int np = s_np, nf = s_nf;
    unsigned M = s_M;

    float    best_z  = -3.0e38f;
    int      best_f  = 0x7fffffff;
    unsigned bestkey = 0u;
    int      hit_i   = (nf > 0) ? 1 : 0;

    for (int q = 0; q < nf; q++) {
        unsigned key = s_key[1023 - q];
        if (key < M || key < bestkey) continue;
        const float4 zr = *(const float4*)(sm + 12288 - 4*(q+1));
        float z = fmaf(zr.x, X, fmaf(zr.y, Y, zr.z));
        int fid = s_fid[1023 - q];
        if (z > best_z) { best_z = z; best_f = fid; bestkey = fkey(z); }
        else if (z == best_z && fid < best_f) { best_f = fid; }
    }
    for (int q = 0; q < np; q++) {
        if (s_key[q] < bestkey) continue;
        const float* d = sm + q*12;
        float4 a = *(const float4*)(d + 0);
        float4 b = *(const float4*)(d + 4);
        float4 c = *(const float4*)(d + 8);
        int fid = s_fid[q];
        float b0 = fmaf(a.x, X, fmaf(a.y, Y, a.z));
        float b1 = fmaf(a.w, X, fmaf(b.x, Y, b.y));
        float b2 = fmaf(b.z, X, fmaf(b.w, Y, c.x));
        float z  = fmaf(c.y, X, fmaf(c.z, Y, c.w));
        if (fminf(b0, fminf(b1, b2)) >= 0.0f) {
            hit_i = 1;
            if (z > best_z) { best_z = z; best_f = fid; bestkey = fkey(z); }
            else if (z == best_z && fid < best_f) { best_f = fid; }
        }
    }

    float u = 0.0f, v = 0.0f;
    if (hit_i) {
        const float* up = g_uvp[r][best_f];
        u = fmaf(up[0], X, fmaf(up[1], Y, up[2]));
        v = fmaf(up[3], X, fmaf(up[4], Y, up[5]));
    }
    float xf = u * 255.0f;
    float yf = (1.0f - v) * 255.0f;
    float x0 = fminf(fmaxf(floorf(xf), 0.0f), 254.0f);
    float y0 = fminf(fmaxf(floorf(yf), 0.0f), 254.0f);
    float fx = xf - x0, fy = yf - y0;
    int xi = (int)x0, yi = (int)y0;
    int base = yi * TEXW + xi;
    #pragma unroll
    for (int cch = 0; cch < 3; cch++) {
        const float* tc = tex + cch * (TEXW*TEXW);
        float t00 = __ldg(tc + base);
        float t01 = __ldg(tc + base + 1);
        float t10 = __ldg(tc + base + TEXW);
        float t11 = __ldg(tc + base + TEXW + 1);
        float val = t00*(1.0f-fx)*(1.0f-fy) + t01*fx*(1.0f-fy)
                  + t10*(1.0f-fx)*fy        + t11*fx*fy;
        g_img[r][cch][i][j] = val;
    }
    g_img[r][3][i][j] = (float)hit_i;
}

// ---------------- tiled fused epilogue ----------------
// grid (16 tiles, NRENDER, 4), block 256 as 32x8.
// z=0 -> MASK (launched FIRST); z=1..3 -> RGB.
// Mask: erode + ONE 21-tap pass per axis; border rows use clip-corrected
// weights computed per-block into shared (s_w21).
__global__ void __launch_bounds__(256) post_kernel(float* __restrict__ out) {
    extern __shared__ float sm[];
    __shared__ float s_w21[11][21];
    const float GW[KSZ] = {GW0,GW1,GW2,GW3,GW4,GW5,GW4,GW3,GW2,GW1,GW0};
    const float W21[21] = {
        2.2103349e-12f, 3.9795740e-10f, 3.1088500e-08f, 1.3467706e-06f,
        3.4812100e-05f, 5.4450606e-04f, 5.1673262e-03f, 2.9729460e-02f,
        1.0378766e-01f, 2.1967292e-01f, 2.8212397e-01f, 2.1967292e-01f,
        1.0378766e-01f, 2.9729460e-02f, 5.1673262e-03f, 5.4450606e-04f,
        3.4812100e-05f, 1.3467706e-06f, 3.1088500e-08f, 3.9795740e-10f,
        2.2103349e-12f };
    int tile = blockIdx.x, r = blockIdx.y;
    int c = (blockIdx.z + 3) & 3;           // z=0 -> c=3 (mask first)
    int tx = tile & 3, ty = tile >> 2;      // 4x4 tiles of 32x32
    int lx = threadIdx.x & 31, ly = threadIdx.x >> 5;   // 32x8

    if (c < 3) {
        // ---- RGB: 43x42 padded halo-5 load, vblur(window) -> 32x42, hblur -> 32x32 ----
        float* bufIn  = sm;                  // 43*42 (row 42 = scratch pad)
        float* bufMid = sm + 43*42;          // 32 rows x 42 cols
        const int gy0 = ty*32 - 5, gx0 = tx*32 - 5;
        for (int li = ly; li < 42; li += 8) {
            int gi = gy0 + li;
            bool rowok = (gi >= 0 && gi < HW);
            {   int lj = lx;       int gj = gx0 + lj;
                bufIn[li*42 + lj] = (rowok && gj >= 0 && gj < HW) ? g_img[r][c][gi][gj] : 0.0f; }
            if (lx < 10) { int lj = lx + 32; int gj = gx0 + lj;
                bufIn[li*42 + lj] = (rowok && gj >= 0 && gj < HW) ? g_img[r][c][gi][gj] : 0.0f; }
        }
        __syncthreads();
        {
            int r0 = ly * 4;
            #pragma unroll
            for (int cb = 0; cb < 2; cb++) {
                int lj = lx + cb*32;
                if (cb == 0 || lx < 10) {
                    float w[KSZ];
                    #pragma unroll
                    for (int k = 0; k < KSZ; k++) w[k] = bufIn[(r0 + k)*42 + lj];
                    #pragma unroll
                    for (int o = 0; o < 4; o++) {
                        float acc = 0.0f;
                        #pragma unroll
                        for (int k = 0; k < KSZ; k++) acc = fmaf(GW[k], w[k], acc);
                        bufMid[(r0 + o)*42 + lj] = acc;
                        #pragma unroll
                        for (int k = 0; k < KSZ-1; k++) w[k] = w[k+1];
                        w[KSZ-1] = bufIn[(r0 + o + KSZ)*42 + lj];
                    }
                }
            }
        }
        __syncthreads();
        for (int li = ly; li < 32; li += 8) {
            float acc = 0.0f;
            #pragma unroll
            for (int k = 0; k < KSZ; k++) acc = fmaf(GW[k], bufMid[li*42 + lx + k], acc);
            out[((r*4 + c) << 14) + (ty*32 + li)*HW + tx*32 + lx] = acc;
        }
        return;
    }

    // ---- MASK: 74x74 halo-21, erode + one 21-tap V pass + one 21-tap H pass ----
    float* bufA = sm;            // 74*74 = 5476
    float* bufB = sm + 5476;
    const int gy0 = ty*32 - 21, gx0 = tx*32 - 21;
    // border weight table: thread e computes entry (b=e/21, t=e%21)
    if (threadIdx.x < 231) {
        int b = threadIdx.x / 21, t = threadIdx.x % 21;
        int jj = b + t - 10;
        float w = 0.0f;
        if (jj >= 0) {
            int kmin = max(0, max(b-5, jj-5));
            int kmax = min(b+5, jj+5);
            for (int k = kmin; k <= kmax; k++)
                w += GW[k-b+5] * GW[jj-k+5];
        }
        s_w21[b][t] = w;
    }
    for (int li = ly; li < 74; li += 8) {
        int gi = gy0 + li;
        bool rowok = (gi >= 0 && gi < HW);
        #pragma unroll
        for (int cb = 0; cb < 3; cb++) {
            int lj = lx + cb*32;
            if (lj < 74) {
                int gj = gx0 + lj;
                bufA[li*74 + lj] = (rowok && gj >= 0 && gj < HW) ? g_img[r][3][gi][gj] : 3.0e38f;
            }
        }
    }
    __syncthreads();
    for (int li = 10 + ly; li < 64; li += 8) {
        int gi = gy0 + li;
        #pragma unroll
        for (int cb = 0; cb < 2; cb++) {
            int lj = 10 + lx + cb*32;
            if (lj < 64) {
                int gj = gx0 + lj;
                const float* rm = bufA + (li-1)*74 + lj;
                const float* r0 = bufA + li*74 + lj;
                const float* rp = bufA + (li+1)*74 + lj;
                float m = fminf(fminf(fminf(rm[-1], rm[0]), fminf(rm[1], r0[-1])),
                                fminf(fminf(r0[0], r0[1]), fminf(fminf(rp[-1], rp[0]), rp[1])));
                bool inimg = (gi >= 0 && gi < HW && gj >= 0 && gj < HW);
                bufB[li*74 + lj] = inimg ? m : 0.0f;
            }
        }
    }
    __syncthreads();
    for (int li = 21 + ly; li < 53; li += 8) {
        int gi = gy0 + li;
        int bi = min(min(gi, 127 - gi), 10);
        #pragma unroll
        for (int cb = 0; cb < 2; cb++) {
            int lj = 10 + lx + cb*32;
            if (lj < 64) {
                float acc = 0.0f;
                if (bi == 10) {
                    #pragma unroll
                    for (int t = 0; t < 21; t++)
                        acc = fmaf(W21[t], bufB[(li + t - 10)*74 + lj], acc);
                } else {
                    bool flip = (gi > 63);
                    const float* wr = s_w21[bi];
                    #pragma unroll
                    for (int t = 0; t < 21; t++)
                        acc = fmaf(wr[flip ? 20 - t : t],
                                   bufB[(li + t - 10)*74 + lj], acc);
                }
                bufA[li*74 + lj] = acc;
            }
        }
    }
    __syncthreads();
    for (int li = 21 + ly; li < 53; li += 8) {
        int lj = 21 + lx;
        int gj = gx0 + lj;
        int bj = min(min(gj, 127 - gj), 10);
        float acc = 0.0f;
        if (bj == 10) {
            #pragma unroll
            for (int t = 0; t < 21; t++)
                acc = fmaf(W21[t], bufA[li*74 + lj + t - 10], acc);
        } else {
            bool flip = (gj > 63);
            const float* wr = s_w21[bj];
            #pragma unroll
            for (int t = 0; t < 21; t++)
                acc = fmaf(wr[flip ? 20 - t : t],
                           bufA[li*74 + lj + t - 10], acc);
        }
        out[((r*4 + 3) << 14) + (gy0 + li)*HW + gj] = acc;
    }
}

// ---------------- launcher ----------------
extern "C" void kernel_launch(void* const* d_in, const int* in_sizes, int n_in,
                              void* d_out, int out_size) {
    const float* vertices  = (const float*)d_in[0];
    const float* quat      = (const float*)d_in[1];
    const float* trans     = (const float*)d_in[2];
    const float* face_ff   = (const float*)d_in[4];
    const float* tex       = (const float*)d_in[5];
    const int*   faces     = (const int*)d_in[6];
    float* out = (float*)d_out;

    static bool attr_set = false;
    if (!attr_set) {
        cudaFuncSetAttribute(raster_kernel, cudaFuncAttributeMaxDynamicSharedMemorySize, 49152);
        cudaFuncSetAttribute(post_kernel,   cudaFuncAttributeMaxDynamicSharedMemorySize, 45056);
        attr_set = true;
    }

    face_kernel<<<dim3(4, NRENDER), 256>>>(vertices, faces, face_ff, quat, trans);
    raster_kernel<<<dim3(64, NRENDER), 256, 49152>>>(tex);
    post_kernel<<<dim3(16, NRENDER, 4), 256, 45056>>>(out);
}

// round 12
// speedup vs baseline: 1.4267x; 1.0067x over previous
#include <cuda_runtime.h>
#include <math.h>

#define NRENDER 16        // NF(2) * T(8)
#define NFACE_C 1024
#define HW 128
#define TEXW 256
#define KSZ 11

// ---------------- device scratch ----------------
__device__ float4 g_plane4[NRENDER][NFACE_C][3]; // {A0,B0,C0,A1},{B1,C1,A2,B2},{C2,zA,zB,zC}
__device__ float4 g_bbox[NRENDER][NFACE_C];      // xmin,xmax,ymin,ymax (dense scan stream)
__device__ float  g_uvp[NRENDER][NFACE_C][8];    // uA,uB,uC,vA,vB,vC,pad,pad
__device__ float  g_img[NRENDER][4][HW][HW];     // rgb + raw mask

// 11-tap gaussian literals (sigma=1), center at index 5
#define GW0 1.4867195147e-06f
#define GW1 1.3383022576e-04f
#define GW2 4.4318484119e-03f
#define GW3 5.3990966513e-02f
#define GW4 2.4197072452e-01f
#define GW5 3.9894228040e-01f

__device__ __forceinline__ unsigned fkey(float f) {
    unsigned u = __float_as_uint(f);
    return u ^ ((u & 0x80000000u) ? 0xFFFFFFFFu : 0x80000000u);
}

// ---------------- quaternion helper ----------------
__device__ __forceinline__ void quat_to_R_dev(const float* q, float scale, float* R) {
    float c = q[0], x = q[1], y = q[2], z = q[3];
    float sin2 = x*x + y*y + z*z;
    float sint = sqrtf(fmaxf(sin2, 1e-12f));
    float tt = 2.0f * ((c < 0.0f) ? atan2f(-sint, -c) : atan2f(sint, c));
    float k = (sin2 > 1e-12f) ? (tt / sint) : 2.0f;
    float ax = k*x*scale, ay = k*y*scale, az = k*z*scale;
    float th = sqrtf(ax*ax + ay*ay + az*az);
    float inv = 1.0f / fmaxf(th, 1e-8f);
    float ux = ax*inv, uy = ay*inv, uz = az*inv;
    float s = sinf(th), co = cosf(th), oc = 1.0f - co;
    R[0] = 1.0f + oc*(-(uy*uy + uz*uz));
    R[1] = -s*uz + oc*(ux*uy);
    R[2] =  s*uy + oc*(ux*uz);
    R[3] =  s*uz + oc*(ux*uy);
    R[4] = 1.0f + oc*(-(ux*ux + uz*uz));
    R[5] = -s*ux + oc*(uy*uz);
    R[6] = -s*uy + oc*(ux*uz);
    R[7] =  s*ux + oc*(uy*uz);
    R[8] = 1.0f + oc*(-(ux*ux + uy*uy));
}

// ---------------- per (render, face) plane setup ----------------
// grid (16, NRENDER), block 64 — 256 blocks spread across all SMs.
// Vertex/uv loads issued BEFORE the serial rotation chain (latency overlap).
__global__ void __launch_bounds__(64) face_kernel(
        const float* __restrict__ verts, const int* __restrict__ faces,
        const float* __restrict__ ff,
        const float* __restrict__ quat, const float* __restrict__ trans) {
    int r = blockIdx.y;
    int fc = blockIdx.x * 64 + threadIdx.x;
    int f = r >> 3, t = r & 7;

    // ---- issue all gathers first (independent of rotation chain) ----
    int vi0 = faces[fc*3 + 0], vi1 = faces[fc*3 + 1], vi2 = faces[fc*3 + 2];
    float V[3][3];
    V[0][0] = verts[vi0*3+0]; V[0][1] = verts[vi0*3+1]; V[0][2] = verts[vi0*3+2];
    V[1][0] = verts[vi1*3+0]; V[1][1] = verts[vi1*3+1]; V[1][2] = verts[vi1*3+2];
    V[2][0] = verts[vi2*3+0]; V[2][1] = verts[vi2*3+1]; V[2][2] = verts[vi2*3+2];
    float u0 = ff[fc*6+0], v0 = ff[fc*6+1];
    float u1 = ff[fc*6+2], v1 = ff[fc*6+3];
    float u2 = ff[fc*6+4], v2 = ff[fc*6+5];

    // ---- serial rotation chain (overlaps the loads above) ----
    float R[12];
    {
        float R0[9], Rs[9];
        quat_to_R_dev(&quat[f*8 + 4], 1.0f, R0);     // q[:,f,1]
        quat_to_R_dev(&quat[f*8 + 0], 0.125f, Rs);   // q[:,f,0]/T/ROT_DIV
        float Rm[9];
        #pragma unroll
        for (int k = 0; k < 9; k++) Rm[k] = R0[k];
        for (int s = 0; s < t; s++) {
            float Nw[9];
            #pragma unroll
            for (int i = 0; i < 3; i++)
                #pragma unroll
                for (int k = 0; k < 3; k++)
                    Nw[i*3+k] = Rm[i*3+0]*Rs[0*3+k] + Rm[i*3+1]*Rs[1*3+k] + Rm[i*3+2]*Rs[2*3+k];
            #pragma unroll
            for (int k = 0; k < 9; k++) Rm[k] = Nw[k];
        }
        #pragma unroll
        for (int k = 0; k < 9; k++) R[k] = Rm[k];
        float ti = (float)t / 7.0f;
        #pragma unroll
        for (int a = 0; a < 3; a++)
            R[9+a] = trans[a*4 + f*2 + 1] + ti * trans[a*4 + f*2 + 0];
    }

    const float invt = 1.0f / tanf(0.3925f);   // 1/tan(FOV/2); px==py since W==H
    float sx[3], sy[3], zz[3], P[3][3];
    #pragma unroll
    for (int k = 0; k < 3; k++) {
        float vx = V[k][0], vy = V[k][1], vz = V[k][2];
        float Xc = R[0]*vx + R[1]*vy + R[2]*vz + R[9];
        float Yc = R[3]*vx + R[4]*vy + R[5]*vz + R[10];
        float Zc = R[6]*vx + R[7]*vy + R[8]*vz + R[11] - 2.0f;   // CAM_D
        P[k][0] = Xc; P[k][1] = Yc; P[k][2] = Zc;
        float invnz = 1.0f / (-Zc);
        sx[k] = (Xc * invt) * invnz;
        sy[k] = (Yc * invt) * invnz;
        zz[k] = Zc;
    }
    float e1x = P[1][0]-P[0][0], e1y = P[1][1]-P[0][1], e1z = P[1][2]-P[0][2];
    float e2x = P[2][0]-P[0][0], e2y = P[2][1]-P[0][1], e2z = P[2][2]-P[0][2];
    float nx = e1y*e2z - e1z*e2y;
    float ny = e1z*e2x - e1x*e2z;
    float nzv = e1x*e2y - e1y*e2x;
    float nz = nzv / (sqrtf(nx*nx + ny*ny + nzv*nzv) + 1e-8f);

    float area = (sx[1]-sx[0])*(sy[2]-sy[0]) - (sy[1]-sy[0])*(sx[2]-sx[0]);
    if (fabsf(area) < 1e-10f) area = 1e-10f;
    float ia = 1.0f / area;
    float A0 = -(sy[2]-sy[1])*ia, B0 = (sx[2]-sx[1])*ia;
    float C0 = ((sy[2]-sy[1])*sx[1] - (sx[2]-sx[1])*sy[1])*ia;
    float A1 = -(sy[0]-sy[2])*ia, B1 = (sx[0]-sx[2])*ia;
    float C1 = ((sy[0]-sy[2])*sx[2] - (sx[0]-sx[2])*sy[2])*ia;
    float A2 = -(sy[1]-sy[0])*ia, B2 = (sx[1]-sx[0])*ia;
    float C2 = ((sy[1]-sy[0])*sx[0] - (sx[1]-sx[0])*sy[0])*ia;
    float zA = A0*zz[0] + A1*zz[1] + A2*zz[2];
    float zB = B0*zz[0] + B1*zz[1] + B2*zz[2];
    float zC = C0*zz[0] + C1*zz[1] + C2*zz[2];

    float xmin, xmax, ymin, ymax;
    if (nz > 0.0f) {
        xmin = fminf(sx[0], fminf(sx[1], sx[2]));
        xmax = fmaxf(sx[0], fmaxf(sx[1], sx[2]));
        ymin = fminf(sy[0], fminf(sy[1], sy[2]));
        ymax = fmaxf(sy[0], fmaxf(sy[1], sy[2]));
    } else {
        xmin = 1e30f; xmax = -1e30f; ymin = 1e30f; ymax = -1e30f;  // never passes cull
    }
    g_plane4[r][fc][0] = make_float4(A0, B0, C0, A1);
    g_plane4[r][fc][1] = make_float4(B1, C1, A2, B2);
    g_plane4[r][fc][2] = make_float4(C2, zA, zB, zC);
    g_bbox[r][fc]      = make_float4(xmin, xmax, ymin, ymax);

    float* up = g_uvp[r][fc];
    up[0] = A0*u0 + A1*u1 + A2*u2;
    up[1] = B0*u0 + B1*u1 + B2*u2;
    up[2] = C0*u0 + C1*u1 + C2*u2;
    up[3] = A0*v0 + A1*v1 + A2*v2;
    up[4] = B0*v0 + B1*v1 + B2*v2;
    up[5] = C0*v0 + C1*v1 + C2*v2;
}

// ---------------- rasterize + texture sample ----------------
// grid: (64 tiles, 16 renders), block 256 = 16x16 px (1 px/thread), 48KB dynamic.
// Dense-bbox compaction scan; block M cull + per-lane running depth cull.
__global__ void __launch_bounds__(256) raster_kernel(const float* __restrict__ tex) {
    extern __shared__ float sm[];         // 12288 floats = 48KB
    __shared__ unsigned s_key[NFACE_C];   // zmax keys: partial at [p], full at [1023-p]
    __shared__ int s_fid[NFACE_C];        // face ids, same layout
    __shared__ int s_np, s_nf;
    __shared__ unsigned s_M;
    int r = blockIdx.y;
    int tile = blockIdx.x;
    int tx = tile & 7, ty = tile >> 3;
    int lj = threadIdx.x & 15, li = threadIdx.x >> 4;
    int j = tx*16 + lj, i = ty*16 + li;
    const float step = 2.0f / 127.0f;
    float X = -1.0f + (float)j * step;
    float Y =  1.0f - (float)i * step;
    float tX0 = -1.0f + (float)(tx*16) * step;
    float tX1 = -1.0f + (float)(tx*16 + 15) * step;
    float tY0 =  1.0f - (float)(ty*16) * step;
    float tY1 =  1.0f - (float)(ty*16 + 15) * step;

    if (threadIdx.x == 0) { s_np = 0; s_nf = 0; s_M = 0u; }
    __syncthreads();

    for (int fc = threadIdx.x; fc < NFACE_C; fc += 256) {
        float4 bb = g_bbox[r][fc];
        if (!(bb.x <= tX1 && bb.y >= tX0 && bb.z <= tY0 && bb.w >= tY1)) continue;
        float4 a = g_plane4[r][fc][0];
        float4 b = g_plane4[r][fc][1];
        float4 c = g_plane4[r][fc][2];
        bool reject = false, full = true;
        {
            float A[3] = {a.x, a.w, b.z}, Bc[3] = {a.y, b.x, b.w}, Cc[3] = {a.z, b.y, c.x};
            #pragma unroll
            for (int e = 0; e < 3; e++) {
                float e00 = fmaf(A[e], tX0, fmaf(Bc[e], tY0, Cc[e]));
                float e01 = fmaf(A[e], tX1, fmaf(Bc[e], tY0, Cc[e]));
                float e10 = fmaf(A[e], tX0, fmaf(Bc[e], tY1, Cc[e]));
                float e11 = fmaf(A[e], tX1, fmaf(Bc[e], tY1, Cc[e]));
                float mn = fminf(fminf(e00, e01), fminf(e10, e11));
                float mx = fmaxf(fmaxf(e00, e01), fmaxf(e10, e11));
                if (mx < 0.0f) reject = true;
                if (mn < 0.0f) full = false;
            }
        }
        if (reject) continue;
        float z00 = fmaf(c.y, tX0, fmaf(c.z, tY0, c.w));
        float z01 = fmaf(c.y, tX1, fmaf(c.z, tY0, c.w));
        float z10 = fmaf(c.y, tX0, fmaf(c.z, tY1, c.w));
        float z11 = fmaf(c.y, tX1, fmaf(c.z, tY1, c.w));
        float zmx = fmaxf(fmaxf(z00, z01), fmaxf(z10, z11));
        if (full) {
            float zmn = fminf(fminf(z00, z01), fminf(z10, z11));
            atomicMax(&s_M, fkey(zmn - 1e-6f));
            int p = atomicAdd(&s_nf, 1);
            float* d = sm + 12288 - 4*(p+1);
            d[0] = c.y; d[1] = c.z; d[2] = c.w;
            s_fid[1023 - p] = fc;
            s_key[1023 - p] = fkey(zmx);
        } else {
            int p = atomicAdd(&s_np, 1);
            float* d = sm + p*12;
            *(float4*)(d + 0) = a;
            *(float4*)(d + 4) = b;
            *(float4*)(d + 8) = c;
            s_fid[p] = fc;
            s_key[p] = fkey(zmx);
        }
    }
    __syncthreads();
    int np = s_np, nf = s_nf;
    unsigned M = s_M;

    float    best_z  = -3.0e38f;
    int      best_f  = 0x7fffffff;
    unsigned bestkey = 0u;
    int      hit_i   = (nf > 0) ? 1 : 0;

    for (int q = 0; q < nf; q++) {
        unsigned key = s_key[1023 - q];
        if (key < M || key < bestkey) continue;
        const float4 zr = *(const float4*)(sm + 12288 - 4*(q+1));
        float z = fmaf(zr.x, X, fmaf(zr.y, Y, zr.z));
        int fid = s_fid[1023 - q];
        if (z > best_z) { best_z = z; best_f = fid; bestkey = fkey(z); }
        else if (z == best_z && fid < best_f) { best_f = fid; }
    }
    for (int q = 0; q < np; q++) {
        if (s_key[q] < bestkey) continue;
        const float* d = sm + q*12;
        float4 a = *(const float4*)(d + 0);
        float4 b = *(const float4*)(d + 4);
        float4 c = *(const float4*)(d + 8);
        int fid = s_fid[q];
        float b0 = fmaf(a.x, X, fmaf(a.y, Y, a.z));
        float b1 = fmaf(a.w, X, fmaf(b.x, Y, b.y));
        float b2 = fmaf(b.z, X, fmaf(b.w, Y, c.x));
        float z  = fmaf(c.y, X, fmaf(c.z, Y, c.w));
        if (fminf(b0, fminf(b1, b2)) >= 0.0f) {
            hit_i = 1;
            if (z > best_z) { best_z = z; best_f = fid; bestkey = fkey(z); }
            else if (z == best_z && fid < best_f) { best_f = fid; }
        }
    }

    float u = 0.0f, v = 0.0f;
    if (hit_i) {
        const float* up = g_uvp[r][best_f];
        u = fmaf(up[0], X, fmaf(up[1], Y, up[2]));
        v = fmaf(up[3], X, fmaf(up[4], Y, up[5]));
    }
    float xf = u * 255.0f;
    float yf = (1.0f - v) * 255.0f;
    float x0 = fminf(fmaxf(floorf(xf), 0.0f), 254.0f);
    float y0 = fminf(fmaxf(floorf(yf), 0.0f), 254.0f);
    float fx = xf - x0, fy = yf - y0;
    int xi = (int)x0, yi = (int)y0;
    int base = yi * TEXW + xi;
    #pragma unroll
    for (int cch = 0; cch < 3; cch++) {
        const float* tc = tex + cch * (TEXW*TEXW);
        float t00 = __ldg(tc + base);
        float t01 = __ldg(tc + base + 1);
        float t10 = __ldg(tc + base + TEXW);
        float t11 = __ldg(tc + base + TEXW + 1);
        float val = t00*(1.0f-fx)*(1.0f-fy) + t01*fx*(1.0f-fy)
                  + t10*(1.0f-fx)*fy        + t11*fx*fy;
        g_img[r][cch][i][j] = val;
    }
    g_img[r][3][i][j] = (float)hit_i;
}

// ---------------- tiled fused epilogue ----------------
// grid (16 tiles, NRENDER, 4), block 256 as 32x8.
// z=0 -> MASK (launched FIRST); z=1..3 -> RGB.
// Mask: erode + ONE 21-tap pass per axis; border rows use clip-corrected
// weights computed per-block into shared (s_w21).
__global__ void __launch_bounds__(256) post_kernel(float* __restrict__ out) {
    extern __shared__ float sm[];
    __shared__ float s_w21[11][21];
    const float GW[KSZ] = {GW0,GW1,GW2,GW3,GW4,GW5,GW4,GW3,GW2,GW1,GW0};
    const float W21[21] = {
        2.2103349e-12f, 3.9795740e-10f, 3.1088500e-08f, 1.3467706e-06f,
        3.4812100e-05f, 5.4450606e-04f, 5.1673262e-03f, 2.9729460e-02f,
        1.0378766e-01f, 2.1967292e-01f, 2.8212397e-01f, 2.1967292e-01f,
        1.0378766e-01f, 2.9729460e-02f, 5.1673262e-03f, 5.4450606e-04f,
        3.4812100e-05f, 1.3467706e-06f, 3.1088500e-08f, 3.9795740e-10f,
        2.2103349e-12f };
    int tile = blockIdx.x, r = blockIdx.y;
    int c = (blockIdx.z + 3) & 3;           // z=0 -> c=3 (mask first)
    int tx = tile & 3, ty = tile >> 2;      // 4x4 tiles of 32x32
    int lx = threadIdx.x & 31, ly = threadIdx.x >> 5;   // 32x8

    if (c < 3) {
        // ---- RGB: 43x42 padded halo-5 load, vblur(window) -> 32x42, hblur -> 32x32 ----
        float* bufIn  = sm;                  // 43*42 (row 42 = scratch pad)
        float* bufMid = sm + 43*42;          // 32 rows x 42 cols
        const int gy0 = ty*32 - 5, gx0 = tx*32 - 5;
        for (int li = ly; li < 42; li += 8) {
            int gi = gy0 + li;
            bool rowok = (gi >= 0 && gi < HW);
            {   int lj = lx;       int gj = gx0 + lj;
                bufIn[li*42 + lj] = (rowok && gj >= 0 && gj < HW) ? g_img[r][c][gi][gj] : 0.0f; }
            if (lx < 10) { int lj = lx + 32; int gj = gx0 + lj;
                bufIn[li*42 + lj] = (rowok && gj >= 0 && gj < HW) ? g_img[r][c][gi][gj] : 0.0f; }
        }
        __syncthreads();
        {
            int r0 = ly * 4;
            #pragma unroll
            for (int cb = 0; cb < 2; cb++) {
                int lj = lx + cb*32;
                if (cb == 0 || lx < 10) {
                    float w[KSZ];
                    #pragma unroll
                    for (int k = 0; k < KSZ; k++) w[k] = bufIn[(r0 + k)*42 + lj];
                    #pragma unroll
                    for (int o = 0; o < 4; o++) {
                        float acc = 0.0f;
                        #pragma unroll
                        for (int k = 0; k < KSZ; k++) acc = fmaf(GW[k], w[k], acc);
                        bufMid[(r0 + o)*42 + lj] = acc;
                        #pragma unroll
                        for (int k = 0; k < KSZ-1; k++) w[k] = w[k+1];
                        w[KSZ-1] = bufIn[(r0 + o + KSZ)*42 + lj];
                    }
                }
            }
        }
        __syncthreads();
        for (int li = ly; li < 32; li += 8) {
            float acc = 0.0f;
            #pragma unroll
            for (int k = 0; k < KSZ; k++) acc = fmaf(GW[k], bufMid[li*42 + lx + k], acc);
            out[((r*4 + c) << 14) + (ty*32 + li)*HW + tx*32 + lx] = acc;
        }
        return;
    }

    // ---- MASK: 74x74 halo-21, erode + one 21-tap V pass + one 21-tap H pass ----
    float* bufA = sm;            // 74*74 = 5476
    float* bufB = sm + 5476;
    const int gy0 = ty*32 - 21, gx0 = tx*32 - 21;
    if (threadIdx.x < 231) {
        int b = threadIdx.x / 21, t = threadIdx.x % 21;
        int jj = b + t - 10;
        float w = 0.0f;
        if (jj >= 0) {
            int kmin = max(0, max(b-5, jj-5));
            int kmax = min(b+5, jj+5);
            for (int k = kmin; k <= kmax; k++)
                w += GW[k-b+5] * GW[jj-k+5];
        }
        s_w21[b][t] = w;
    }
    for (int li = ly; li < 74; li += 8) {
        int gi = gy0 + li;
        bool rowok = (gi >= 0 && gi < HW);
        #pragma unroll
        for (int cb = 0; cb < 3; cb++) {
            int lj = lx + cb*32;
            if (lj < 74) {
                int gj = gx0 + lj;
                bufA[li*74 + lj] = (rowok && gj >= 0 && gj < HW) ? g_img[r][3][gi][gj] : 3.0e38f;
            }
        }
    }
    __syncthreads();
    for (int li = 10 + ly; li < 64; li += 8) {
        int gi = gy0 + li;
        #pragma unroll
        for (int cb = 0; cb < 2; cb++) {
            int lj = 10 + lx + cb*32;
            if (lj < 64) {
                int gj = gx0 + lj;
                const float* rm = bufA + (li-1)*74 + lj;
                const float* r0 = bufA + li*74 + lj;
                const float* rp = bufA + (li+1)*74 + lj;
                float m = fminf(fminf(fminf(rm[-1], rm[0]), fminf(rm[1], r0[-1])),
                                fminf(fminf(r0[0], r0[1]), fminf(fminf(rp[-1], rp[0]), rp[1])));
                bool inimg = (gi >= 0 && gi < HW && gj >= 0 && gj < HW);
                bufB[li*74 + lj] = inimg ? m : 0.0f;
            }
        }
    }
    __syncthreads();
    for (int li = 21 + ly; li < 53; li += 8) {
        int gi = gy0 + li;
        int bi = min(min(gi, 127 - gi), 10);
        #pragma unroll
        for (int cb = 0; cb < 2; cb++) {
            int lj = 10 + lx + cb*32;
            if (lj < 64) {
                float acc = 0.0f;
                if (bi == 10) {
                    #pragma unroll
                    for (int t = 0; t < 21; t++)
                        acc = fmaf(W21[t], bufB[(li + t - 10)*74 + lj], acc);
                } else {
                    bool flip = (gi > 63);
                    const float* wr = s_w21[bi];
                    #pragma unroll
                    for (int t = 0; t < 21; t++)
                        acc = fmaf(wr[flip ? 20 - t : t],
                                   bufB[(li + t - 10)*74 + lj], acc);
                }
                bufA[li*74 + lj] = acc;
            }
        }
    }
    __syncthreads();
    for (int li = 21 + ly; li < 53; li += 8) {
        int lj = 21 + lx;
        int gj = gx0 + lj;
        int bj = min(min(gj, 127 - gj), 10);
        float acc = 0.0f;
        if (bj == 10) {
            #pragma unroll
            for (int t = 0; t < 21; t++)
                acc = fmaf(W21[t], bufA[li*74 + lj + t - 10], acc);
        } else {
            bool flip = (gj > 63);
            const float* wr = s_w21[bj];
            #pragma unroll
            for (int t = 0; t < 21; t++)
                acc = fmaf(wr[flip ? 20 - t : t],
                           bufA[li*74 + lj + t - 10], acc);
        }
        out[((r*4 + 3) << 14) + (gy0 + li)*HW + gj] = acc;
    }
}

// ---------------- launcher ----------------
extern "C" void kernel_launch(void* const* d_in, const int* in_sizes, int n_in,
                              void* d_out, int out_size) {
    const float* vertices  = (const float*)d_in[0];
    const float* quat      = (const float*)d_in[1];
    const float* trans     = (const float*)d_in[2];
    const float* face_ff   = (const float*)d_in[4];
    const float* tex       = (const float*)d_in[5];
    const int*   faces     = (const int*)d_in[6];
    float* out = (float*)d_out;

    static bool attr_set = false;
    if (!attr_set) {
        cudaFuncSetAttribute(raster_kernel, cudaFuncAttributeMaxDynamicSharedMemorySize, 49152);
        cudaFuncSetAttribute(post_kernel,   cudaFuncAttributeMaxDynamicSharedMemorySize, 45056);
        attr_set = true;
    }

    face_kernel<<<dim3(16, NRENDER), 64>>>(vertices, faces, face_ff, quat, trans);
    raster_kernel<<<dim3(64, NRENDER), 256, 49152>>>(tex);
    post_kernel<<<dim3(16, NRENDER, 4), 256, 45056>>>(out);
}